// round 12
// baseline (speedup 1.0000x reference)
#include <cuda_runtime.h>

// ---------------------------------------------------------------------------
#define NMAX   65536
#define MNBR   12
#define ATOMF  64
#define INF_   192
#define BD     384
#define GBD    256
#define APB    32      // atoms per block (8 groups of 4)

// ---------------------------------------------------------------------------
__device__ float g_Pself[NMAX * INF_];               // 48 MB
__device__ float g_Pnbr [NMAX * INF_];               // 48 MB
__device__ float g_att  [(size_t)NMAX * MNBR * 64];  // 201 MB (tf32-rounded)
__device__ float g_s    [NMAX * ATOMF];              // 16 MB
__device__ float g_WEt  [192 * 64];                  // edge weights, tf32
__device__ float g_Wall [384 * 64];                  // [self|nbr] proj weights, tf32
__device__ float g_Wfut [128 * 64];                  // fused W_fc@WO, tf32
__device__ float g_S    [64 * 64];
__device__ float g_svec [64];
__device__ float g_sum2[64], g_sq2[64];
__device__ float g_sc1[128], g_sh1[128], g_sc2[64], g_sh2[64];

// ---------------------------------------------------------------------------
__device__ __forceinline__ float tf32r(float x) {
    unsigned u; asm("cvt.rna.tf32.f32 %0, %1;" : "=r"(u) : "f"(x));
    return __uint_as_float(u);
}
__device__ __forceinline__ void mma8(float d[4], float a0, float a1, float a2, float a3,
                                     float b0, float b1) {
    unsigned A0 = __float_as_uint(a0), A1 = __float_as_uint(a1);
    unsigned A2 = __float_as_uint(a2), A3 = __float_as_uint(a3);
    unsigned B0 = __float_as_uint(b0), B1 = __float_as_uint(b1);
    asm volatile("mma.sync.aligned.m16n8k8.row.col.f32.tf32.tf32.f32 "
                 "{%0,%1,%2,%3}, {%4,%5,%6,%7}, {%8,%9}, {%0,%1,%2,%3};"
                 : "+f"(d[0]), "+f"(d[1]), "+f"(d[2]), "+f"(d[3])
                 : "r"(A0), "r"(A1), "r"(A2), "r"(A3), "r"(B0), "r"(B1));
}
__device__ __forceinline__ float sigf(float x) { return 1.f / (1.f + __expf(-x)); }
__device__ __forceinline__ float spf2(float x) {
    return fmaxf(x, 0.f) + __logf(1.f + __expf(-fabsf(x)));
}

__global__ void k_dummy(int x) { if (x == 12345) g_svec[63] += 0.f; }

// ---------------------------------------------------------------------------
// K_prep: tf32-round WEt, Wall; fuse W_fc@WO; zero stats. grid 192 x 256.
// ---------------------------------------------------------------------------
__global__ void k_prep(const float* __restrict__ WK, const float* __restrict__ WQ,
                       const float* __restrict__ WV, const float* __restrict__ Wfc,
                       const float* __restrict__ WO) {
    int t = threadIdx.x;
    if (blockIdx.x == 0 && t < 64) {
        g_sum2[t] = 0.f; g_sq2[t] = 0.f; g_svec[t] = 0.f;
    }
    int o = blockIdx.x * 256 + t;
    if (o < 12288) {
        int j = o >> 6, f = o & 63;
        const float* W = (j < 64) ? WK : ((j < 128) ? WQ : WV);
        g_WEt[o] = tf32r(W[(j & 63) * INF_ + 128 + f]);
    } else if (o < 36864) {
        int p = o - 12288;
        int j = p >> 6, f = p & 63;
        int half = (j >= 192);
        int jj = half ? j - 192 : j;
        const float* W = (jj < 64) ? WK : ((jj < 128) ? WQ : WV);
        g_Wall[p] = tf32r(W[(jj & 63) * INF_ + (half ? 64 : 0) + f]);
    } else if (o < 45056) {
        int p = o - 36864;
        int g = p >> 6, a = p & 63;
        const float* wr = Wfc + g * 256;
        float acc = 0.f;
        #pragma unroll 8
        for (int q = 0; q < 256; q++) acc += wr[q] * WO[q * 64 + a];
        g_Wfut[p] = tf32r(acc);
    } else if (o < 49152) {
        g_S[o - 45056] = 0.f;
    }
}

// ---------------------------------------------------------------------------
// K_projT: tensorized per-atom projections (single-term tf32).
// ---------------------------------------------------------------------------
__global__ __launch_bounds__(384, 2) void k_projT(const float* __restrict__ atom, int N) {
    __shared__ float sAT[48 * 68];
    int tid = threadIdx.x, wid = tid >> 5, lane = tid & 31;
    int qid = lane >> 2, tq = lane & 3;
    int n0 = blockIdx.x * 48;

    #pragma unroll
    for (int s = 0; s < 8; s++) {
        int i = tid + s * 384;
        int r = i >> 6, c = i & 63;
        int n = n0 + r;
        float v = (n < N) ? atom[(size_t)n * 64 + c] : 0.f;
        sAT[r * 68 + c] = tf32r(v);
    }
    __syncthreads();

    #pragma unroll
    for (int half = 0; half < 2; half++) {
        const float* Wsrc = g_Wall + (half * 192 + wid * 16) * 64;
        float aw[8][4];
        #pragma unroll
        for (int ks = 0; ks < 8; ks++) {
            int f0 = ks * 8 + tq;
            aw[ks][0] = Wsrc[qid * 64 + f0];
            aw[ks][1] = Wsrc[(qid + 8) * 64 + f0];
            aw[ks][2] = Wsrc[qid * 64 + f0 + 4];
            aw[ks][3] = Wsrc[(qid + 8) * 64 + f0 + 4];
        }
        float* ob = half ? g_Pnbr : g_Pself;
        #pragma unroll
        for (int nt = 0; nt < 6; nt++) {
            float d[4] = {0.f, 0.f, 0.f, 0.f};
            const float* ar = sAT + (8 * nt + qid) * 68;
            #pragma unroll
            for (int ks = 0; ks < 8; ks++)
                mma8(d, aw[ks][0], aw[ks][1], aw[ks][2], aw[ks][3],
                     ar[ks * 8 + tq], ar[ks * 8 + tq + 4]);
            int r0  = 8 * nt + 2 * tq;
            int ch0 = wid * 16 + qid;
            if (n0 + r0 < N) {
                ob[(size_t)(n0 + r0) * INF_ + ch0]     = d[0];
                ob[(size_t)(n0 + r0) * INF_ + ch0 + 8] = d[2];
            }
            if (n0 + r0 + 1 < N) {
                ob[(size_t)(n0 + r0 + 1) * INF_ + ch0]     = d[1];
                ob[(size_t)(n0 + r0 + 1) * INF_ + ch0 + 8] = d[3];
            }
        }
    }
}

// ---------------------------------------------------------------------------
// K_main: champion pipeline + fused S/svec stats (P6).
//   P1 vector gather | P2 edge MMA | P3 logits+softmax / NF prefetch
//   P5 w@V MMA -> sATT | P6 S-MMA (w0-7) + float4 att store & svec (w8-11)
// ---------------------------------------------------------------------------
#define O_NF    0                 // 2 x 48x68 = 6528
#define O_KQV   6528              // 52 x 204 = 10608
#define O_LG    17136             // 4 x 272  = 1088
#define O_J     18224             // 2 x 48 ints = 96
#define O_ATT   18320             // 48 x 68 = 3264
#define SMEM_FLOATS 21584
#define SMEM_MAIN_BYTES (SMEM_FLOATS * 4)

__global__ __launch_bounds__(BD, 2) void k_main(const float* __restrict__ nbr,
                                                const int*   __restrict__ idx,
                                                int N) {
    extern __shared__ float sm[];
    float* sNF0 = sm + O_NF;
    float* sNF1 = sm + O_NF + 3264;
    float* sKQV = sm + O_KQV;
    float* sLG  = sm + O_LG;
    int*   sJ0  = (int*)(sm + O_J);
    int*   sJ1  = sJ0 + 48;
    float* sATT = sm + O_ATT;

    int tid  = threadIdx.x;
    int wid  = tid >> 5;
    int lane = tid & 31;
    int qid  = lane >> 2;
    int tq   = lane & 3;

    float aw[8][4];
    {
        int ch0 = 16 * wid + qid;
        #pragma unroll
        for (int ks = 0; ks < 8; ks++) {
            int f0 = ks * 8 + tq;
            aw[ks][0] = g_WEt[ch0 * 64 + f0];
            aw[ks][1] = g_WEt[(ch0 + 8) * 64 + f0];
            aw[ks][2] = g_WEt[ch0 * 64 + f0 + 4];
            aw[ks][3] = g_WEt[(ch0 + 8) * 64 + f0 + 4];
        }
    }

    // persistent S accumulators (warps 0-7) / svec (warps 8-11)
    float sacc[4][4];
    #pragma unroll
    for (int i = 0; i < 4; i++)
        #pragma unroll
        for (int j = 0; j < 4; j++) sacc[i][j] = 0.f;
    float sv0 = 0.f, sv1 = 0.f, sv2 = 0.f, sv3 = 0.f;

    // zero pad rows 48-51 of sKQV
    for (int i = tid; i < 4 * 204; i += BD) sKQV[48 * 204 + i] = 0.f;

    // prologue: NF(0) + sJ(0)
    {
        int n00 = blockIdx.x * APB;
        const float4* nb4 = (const float4*)(nbr + (size_t)n00 * 768);
        #pragma unroll
        for (int s = 0; s < 2; s++) {
            int v = tid + s * 384;          // 768 float4
            float4 x = nb4[v];
            x.x = tf32r(x.x); x.y = tf32r(x.y); x.z = tf32r(x.z); x.w = tf32r(x.w);
            *(float4*)&sNF0[(v >> 4) * 68 + (v & 15) * 4] = x;
        }
        if (tid < 48) sJ0[tid] = idx[n00 * MNBR + tid];
    }
    __syncthreads();

    for (int grp = 0; grp < 8; grp++) {
        int n0 = blockIdx.x * APB + grp * 4;
        if (n0 >= N) break;
        float* sNF  = (grp & 1) ? sNF1 : sNF0;
        int*   sJc  = (grp & 1) ? sJ1  : sJ0;
        float* sNFn = (grp & 1) ? sNF0 : sNF1;
        int*   sJn  = (grp & 1) ? sJ0  : sJ1;

        // ---- P1: vector gather -> sKQV (f32) ----
        #pragma unroll
        for (int s = 0; s < 6; s++) {
            int v  = tid + s * 384;          // 2304 float4 = 48 edges x 48
            int e  = v / 48;
            int c4 = (v - e * 48) * 4;
            int j  = sJc[e];
            int at = e / 12;
            float4 pn = *(const float4*)&g_Pnbr [(size_t)j * INF_ + c4];
            float4 ps = *(const float4*)&g_Pself[(size_t)(n0 + at) * INF_ + c4];
            float4 r;
            r.x = pn.x + ps.x; r.y = pn.y + ps.y;
            r.z = pn.z + ps.z; r.w = pn.w + ps.w;
            *(float4*)&sKQV[e * 204 + c4] = r;
        }
        __syncthreads();

        // ---- P2: edge MMA accumulating gather; epilogue tf32 ----
        {
            int ch0 = 16 * wid + qid;
            #pragma unroll
            for (int nt = 0; nt < 6; nt++) {
                int e0 = 8 * nt + 2 * tq;
                float d[4];
                d[0] = sKQV[e0 * 204 + ch0];
                d[1] = sKQV[(e0 + 1) * 204 + ch0];
                d[2] = sKQV[e0 * 204 + ch0 + 8];
                d[3] = sKQV[(e0 + 1) * 204 + ch0 + 8];
                const float* nrow = sNF + (8 * nt + qid) * 68;
                #pragma unroll
                for (int ks = 0; ks < 8; ks++) {
                    float b0 = nrow[ks * 8 + tq];
                    float b1 = nrow[ks * 8 + tq + 4];
                    mma8(d, aw[ks][0], aw[ks][1], aw[ks][2], aw[ks][3], b0, b1);
                }
                sKQV[e0 * 204 + ch0]           = tf32r(d[0]);
                sKQV[(e0 + 1) * 204 + ch0]     = tf32r(d[1]);
                sKQV[e0 * 204 + ch0 + 8]       = tf32r(d[2]);
                sKQV[(e0 + 1) * 204 + ch0 + 8] = tf32r(d[3]);
            }
        }
        __syncthreads();

        // ---- P3: logits+softmax (warps 0-3) | NF/idx prefetch (warps 4-11) ----
        if (wid < 4) {
            int a  = wid;
            int r0 = 12 * a;
            float d0[4] = {0.f, 0.f, 0.f, 0.f};
            float d1[4] = {0.f, 0.f, 0.f, 0.f};
            #pragma unroll
            for (int s = 0; s < 8; s++) {
                int f = 8 * s + tq;
                float a0 = sKQV[(r0 + qid) * 204 + f];
                float a1 = sKQV[(r0 + qid + 8) * 204 + f];
                float a2 = sKQV[(r0 + qid) * 204 + f + 4];
                float a3 = sKQV[(r0 + qid + 8) * 204 + f + 4];
                float b00 = sKQV[(r0 + qid) * 204 + 64 + f];
                float b01 = sKQV[(r0 + qid) * 204 + 64 + f + 4];
                float b10 = sKQV[(r0 + 8 + qid) * 204 + 64 + f];
                float b11 = sKQV[(r0 + 8 + qid) * 204 + 64 + f + 4];
                mma8(d0, a0, a1, a2, a3, b00, b01);
                mma8(d1, a0, a1, a2, a3, b10, b11);
            }
            float* lg = sLG + a * 272;
            bool colBad = (tq >= 2);
            {
                float l[4];
                l[0] = d0[0] * 0.125f; l[1] = d0[1] * 0.125f;
                l[2] = colBad ? -1e30f : d1[0] * 0.125f;
                l[3] = colBad ? -1e30f : d1[1] * 0.125f;
                float mx = fmaxf(fmaxf(l[0], l[1]), fmaxf(l[2], l[3]));
                mx = fmaxf(mx, __shfl_xor_sync(0xffffffffu, mx, 1));
                mx = fmaxf(mx, __shfl_xor_sync(0xffffffffu, mx, 2));
                float e0 = __expf(l[0] - mx), e1 = __expf(l[1] - mx);
                float e2 = __expf(l[2] - mx), e3 = __expf(l[3] - mx);
                float s = e0 + e1 + e2 + e3;
                s += __shfl_xor_sync(0xffffffffu, s, 1);
                s += __shfl_xor_sync(0xffffffffu, s, 2);
                float inv = 1.f / s;
                lg[qid * 17 + 2 * tq]         = tf32r(e0 * inv);
                lg[qid * 17 + 2 * tq + 1]     = tf32r(e1 * inv);
                lg[qid * 17 + 8 + 2 * tq]     = tf32r(e2 * inv);
                lg[qid * 17 + 8 + 2 * tq + 1] = tf32r(e3 * inv);
            }
            {
                bool rowOk = (qid < 4);
                float l[4];
                l[0] = d0[2] * 0.125f; l[1] = d0[3] * 0.125f;
                l[2] = colBad ? -1e30f : d1[2] * 0.125f;
                l[3] = colBad ? -1e30f : d1[3] * 0.125f;
                float mx = fmaxf(fmaxf(l[0], l[1]), fmaxf(l[2], l[3]));
                mx = fmaxf(mx, __shfl_xor_sync(0xffffffffu, mx, 1));
                mx = fmaxf(mx, __shfl_xor_sync(0xffffffffu, mx, 2));
                float e0 = __expf(l[0] - mx), e1 = __expf(l[1] - mx);
                float e2 = __expf(l[2] - mx), e3 = __expf(l[3] - mx);
                float s = e0 + e1 + e2 + e3;
                s += __shfl_xor_sync(0xffffffffu, s, 1);
                s += __shfl_xor_sync(0xffffffffu, s, 2);
                float inv = rowOk ? (1.f / s) : 0.f;
                lg[(qid + 8) * 17 + 2 * tq]         = tf32r(e0 * inv);
                lg[(qid + 8) * 17 + 2 * tq + 1]     = tf32r(e1 * inv);
                lg[(qid + 8) * 17 + 8 + 2 * tq]     = tf32r(e2 * inv);
                lg[(qid + 8) * 17 + 8 + 2 * tq + 1] = tf32r(e3 * inv);
            }
        } else if (grp < 7) {
            int n1 = n0 + 4;
            if (n1 < N) {
                int t2 = tid - 128;            // 0..255
                const float4* nb4 = (const float4*)(nbr + (size_t)n1 * 768);
                #pragma unroll
                for (int s = 0; s < 3; s++) {
                    int v = t2 + s * 256;      // 768 float4
                    float4 x = nb4[v];
                    x.x = tf32r(x.x); x.y = tf32r(x.y); x.z = tf32r(x.z); x.w = tf32r(x.w);
                    *(float4*)&sNFn[(v >> 4) * 68 + (v & 15) * 4] = x;
                }
                if (t2 < 48) sJn[t2] = idx[n1 * MNBR + t2];
            }
        }
        __syncthreads();

        // ---- P5: attn = W @ V MMA -> sATT (smem) ----
        if (wid < 8) {
            int a = wid >> 1;
            int ntb = (wid & 1) * 4;
            const float* lg = sLG + a * 272;
            float af[2][4];
            #pragma unroll
            for (int s = 0; s < 2; s++) {
                int k = 8 * s + tq;
                af[s][0] = lg[qid * 17 + k];
                af[s][1] = lg[(qid + 8) * 17 + k];
                af[s][2] = lg[qid * 17 + k + 4];
                af[s][3] = lg[(qid + 8) * 17 + k + 4];
            }
            #pragma unroll
            for (int j = 0; j < 4; j++) {
                int nt = ntb + j;
                float d[4] = {0.f, 0.f, 0.f, 0.f};
                #pragma unroll
                for (int s = 0; s < 2; s++) {
                    int kr = 12 * a + 8 * s + tq;
                    float b0 = sKQV[kr * 204 + 128 + 8 * nt + qid];
                    float b1 = sKQV[(kr + 4) * 204 + 128 + 8 * nt + qid];
                    mma8(d, af[s][0], af[s][1], af[s][2], af[s][3], b0, b1);
                }
                int col = 8 * nt + 2 * tq;
                int row = 12 * a + qid;
                float2 w0 = {tf32r(d[0]), tf32r(d[1])};
                *(float2*)&sATT[row * 68 + col] = w0;
                if (qid < 4) {
                    float2 w1 = {tf32r(d[2]), tf32r(d[3])};
                    *(float2*)&sATT[(row + 8) * 68 + col] = w1;
                }
            }
        }
        __syncthreads();

        // ---- P6: S-MMA (warps 0-7) | float4 att store + svec (warps 8-11) ----
        if (wid < 8) {
            int mt  = wid >> 1;
            int ntb = (wid & 1) * 4;
            #pragma unroll
            for (int ks = 0; ks < 6; ks++) {
                int kr = 8 * ks + tq;
                float a0 = sATT[kr * 68 + 16 * mt + qid];
                float a1 = sATT[kr * 68 + 16 * mt + qid + 8];
                float a2 = sATT[(kr + 4) * 68 + 16 * mt + qid];
                float a3 = sATT[(kr + 4) * 68 + 16 * mt + qid + 8];
                #pragma unroll
                for (int j = 0; j < 4; j++) {
                    int nt = ntb + j;
                    float b0 = sATT[kr * 68 + 8 * nt + qid];
                    float b1 = sATT[(kr + 4) * 68 + 8 * nt + qid];
                    mma8(sacc[j], a0, a1, a2, a3, b0, b1);
                }
            }
        } else {
            int t2 = tid - 256;                // 0..127
            float* go = g_att + (size_t)n0 * 768;
            #pragma unroll
            for (int s6 = 0; s6 < 6; s6++) {
                int v = t2 + s6 * 128;         // 768 float4
                float4 x = *(const float4*)&sATT[(v >> 4) * 68 + (v & 15) * 4];
                *(float4*)&go[v * 4] = x;
                sv0 += x.x; sv1 += x.y; sv2 += x.z; sv3 += x.w;
            }
        }
        __syncthreads();   // sATT/sKQV reused next group
    }

    // ---- epilogue: accumulate S + svec ----
    if (wid < 8) {
        int mt  = wid >> 1;
        int ntb = (wid & 1) * 4;
        #pragma unroll
        for (int j = 0; j < 4; j++) {
            int c1 = 16 * mt + qid;
            int c2 = 8 * (ntb + j) + 2 * tq;
            atomicAdd(&g_S[c1 * 64 + c2],           sacc[j][0]);
            atomicAdd(&g_S[c1 * 64 + c2 + 1],       sacc[j][1]);
            atomicAdd(&g_S[(c1 + 8) * 64 + c2],     sacc[j][2]);
            atomicAdd(&g_S[(c1 + 8) * 64 + c2 + 1], sacc[j][3]);
        }
    } else {
        int c4 = ((tid - 256) & 15) * 4;
        atomicAdd(&g_svec[c4],     sv0);
        atomicAdd(&g_svec[c4 + 1], sv1);
        atomicAdd(&g_svec[c4 + 2], sv2);
        atomicAdd(&g_svec[c4 + 3], sv3);
    }
}

// ---------------------------------------------------------------------------
// K_bn1: moment trick with double-precision reduction.
// ---------------------------------------------------------------------------
__global__ void k_bn1(const float* __restrict__ bfc, const float* __restrict__ g1,
                      const float* __restrict__ b1, double invCnt) {
    __shared__ float sS[64 * 65];
    __shared__ float sw[64];
    __shared__ double red[4];
    int g = blockIdx.x;
    int i = threadIdx.x;
    sw[i] = g_Wfut[g * 64 + i];
    for (int l = i; l < 4096; l += 64)
        sS[(l >> 6) * 65 + (l & 63)] = g_S[l];
    __syncthreads();
    double y = 0.0;
    #pragma unroll 8
    for (int j = 0; j < 64; j++) y += (double)sS[i * 65 + j] * (double)sw[j];
    y *= (double)sw[i];
    double p = (double)sw[i] * (double)g_svec[i];
    #pragma unroll
    for (int off = 16; off > 0; off >>= 1) {
        y += __shfl_xor_sync(0xffffffffu, y, off);
        p += __shfl_xor_sync(0xffffffffu, p, off);
    }
    if ((i & 31) == 0) { red[(i >> 5) * 2] = y; red[(i >> 5) * 2 + 1] = p; }
    __syncthreads();
    if (i == 0) {
        double quad = red[0] + red[2];
        double lin  = red[1] + red[3];
        double b    = (double)bfc[g];
        double mean = lin * invCnt + b;
        double ex2  = (quad + 2.0 * b * lin) * invCnt + b * b;
        double var  = ex2 - mean * mean;
        double sc   = (double)g1[g] / sqrt(var + 1e-5);
        g_sc1[g] = (float)sc;
        g_sh1[g] = (float)((double)b1[g] - mean * sc);
    }
}

// ---------------------------------------------------------------------------
// K_gate: register-resident gated + activation + per-atom reduction.
// ---------------------------------------------------------------------------
#define SMEM_GATE_FLOATS (48 * 68)
#define SMEM_GATE_BYTES (SMEM_GATE_FLOATS * 4)

__global__ __launch_bounds__(GBD, 3) void k_gate(const float* __restrict__ bfc, int N) {
    extern __shared__ float sm[];
    float* sA = sm;

    int tid  = threadIdx.x;
    int wid  = tid >> 5;
    int lane = tid & 31;
    int qid  = lane >> 2;
    int tq   = lane & 3;

    float bwf[8][2], bwh[8][2];
    float bbf[2], bbh[2];
    {
        int rf = wid * 8 + qid;
        int rh = 64 + wid * 8 + qid;
        float scf = g_sc1[rf], sch = g_sc1[rh];
        #pragma unroll
        for (int ks = 0; ks < 8; ks++) {
            bwf[ks][0] = tf32r(g_Wfut[rf * 64 + ks * 8 + tq] * scf);
            bwf[ks][1] = tf32r(g_Wfut[rf * 64 + ks * 8 + tq + 4] * scf);
            bwh[ks][0] = tf32r(g_Wfut[rh * 64 + ks * 8 + tq] * sch);
            bwh[ks][1] = tf32r(g_Wfut[rh * 64 + ks * 8 + tq + 4] * sch);
        }
        int cf = wid * 8 + 2 * tq;
        bbf[0] = bfc[cf]          * g_sc1[cf]          + g_sh1[cf];
        bbf[1] = bfc[cf + 1]      * g_sc1[cf + 1]      + g_sh1[cf + 1];
        bbh[0] = bfc[64 + cf]     * g_sc1[64 + cf]     + g_sh1[64 + cf];
        bbh[1] = bfc[64 + cf + 1] * g_sc1[64 + cf + 1] + g_sh1[64 + cf + 1];
    }
    float ls0 = 0.f, ls1 = 0.f, lq0 = 0.f, lq1 = 0.f;

    for (int grp = 0; grp < 8; grp++) {
        int n0 = blockIdx.x * APB + grp * 4;
        if (n0 >= N) break;

        const float4* ai4 = (const float4*)(g_att + (size_t)n0 * 768);
        #pragma unroll
        for (int s = 0; s < 3; s++) {
            int v = tid + s * GBD;           // 768 float4
            float4 x = ai4[v];
            *(float4*)&sA[(v >> 4) * 68 + (v & 15) * 4] = x;
        }
        __syncthreads();

        float acc[4][2];
        #pragma unroll
        for (int a = 0; a < 4; a++) { acc[a][0] = 0.f; acc[a][1] = 0.f; }

        #pragma unroll
        for (int mt = 0; mt < 3; mt++) {
            int r0 = 16 * mt + qid;
            float a[8][4];
            #pragma unroll
            for (int ks = 0; ks < 8; ks++) {
                int c0 = ks * 8 + tq;
                a[ks][0] = sA[r0 * 68 + c0];
                a[ks][1] = sA[(r0 + 8) * 68 + c0];
                a[ks][2] = sA[r0 * 68 + c0 + 4];
                a[ks][3] = sA[(r0 + 8) * 68 + c0 + 4];
            }
            float f[4] = {0.f, 0.f, 0.f, 0.f};
            float h[4] = {0.f, 0.f, 0.f, 0.f};
            #pragma unroll
            for (int ks = 0; ks < 8; ks++) {
                mma8(f, a[ks][0], a[ks][1], a[ks][2], a[ks][3], bwf[ks][0], bwf[ks][1]);
                mma8(h, a[ks][0], a[ks][1], a[ks][2], a[ks][3], bwh[ks][0], bwh[ks][1]);
            }
            float v0 = sigf(f[0] + bbf[0]) * spf2(h[0] + bbh[0]);
            float v1 = sigf(f[1] + bbf[1]) * spf2(h[1] + bbh[1]);
            float v2 = sigf(f[2] + bbf[0]) * spf2(h[2] + bbh[0]);
            float v3 = sigf(f[3] + bbf[1]) * spf2(h[3] + bbh[1]);
            if (mt == 0) {
                acc[0][0] += v0; acc[0][1] += v1;
                if (qid < 4) { acc[0][0] += v2; acc[0][1] += v3; }
                else         { acc[1][0] += v2; acc[1][1] += v3; }
            } else if (mt == 1) {
                acc[1][0] += v0; acc[1][1] += v1;
                acc[2][0] += v2; acc[2][1] += v3;
            } else {
                if (qid < 4) { acc[2][0] += v0; acc[2][1] += v1; }
                else         { acc[3][0] += v0; acc[3][1] += v1; }
                acc[3][0] += v2; acc[3][1] += v3;
            }
        }

        #pragma unroll
        for (int a = 0; a < 4; a++) {
            #pragma unroll
            for (int c = 0; c < 2; c++) {
                float v = acc[a][c];
                v += __shfl_xor_sync(0xffffffffu, v, 4);
                v += __shfl_xor_sync(0xffffffffu, v, 8);
                v += __shfl_xor_sync(0xffffffffu, v, 16);
                acc[a][c] = v;
            }
        }
        if (lane < 4) {
            int col = wid * 8 + 2 * lane;
            #pragma unroll
            for (int a = 0; a < 4; a++) {
                g_s[(size_t)(n0 + a) * 64 + col]     = acc[a][0];
                g_s[(size_t)(n0 + a) * 64 + col + 1] = acc[a][1];
                ls0 += acc[a][0]; lq0 += acc[a][0] * acc[a][0];
                ls1 += acc[a][1]; lq1 += acc[a][1] * acc[a][1];
            }
        }
        __syncthreads();
    }
    if (lane < 4) {
        int col = wid * 8 + 2 * lane;
        atomicAdd(&g_sum2[col],     ls0);
        atomicAdd(&g_sq2[col],      lq0);
        atomicAdd(&g_sum2[col + 1], ls1);
        atomicAdd(&g_sq2[col + 1],  lq1);
    }
}

// ---------------------------------------------------------------------------
// K_bn2: double-precision var computation.
// ---------------------------------------------------------------------------
__global__ void k_bn2(const float* __restrict__ g2, const float* __restrict__ b2, double invCnt) {
    int t = threadIdx.x;
    double m = (double)g_sum2[t] * invCnt;
    double v = (double)g_sq2[t] * invCnt - m * m;
    double sc = (double)g2[t] / sqrt(v + 1e-5);
    g_sc2[t] = (float)sc;
    g_sh2[t] = (float)((double)b2[t] - m * sc);
}

__global__ void k_final(const float* __restrict__ atom, float* __restrict__ out, int nVec) {
    int i = blockIdx.x * blockDim.x + threadIdx.x;
    if (i >= nVec) return;
    int c4 = (i & 15) * 4;
    float4 a = *(const float4*)&atom[(size_t)i * 4];
    float4 s = *(const float4*)&g_s[(size_t)i * 4];
    float4 o;
    o.x = spf2(a.x + s.x * g_sc2[c4]     + g_sh2[c4]);
    o.y = spf2(a.y + s.y * g_sc2[c4 + 1] + g_sh2[c4 + 1]);
    o.z = spf2(a.z + s.z * g_sc2[c4 + 2] + g_sh2[c4 + 2]);
    o.w = spf2(a.w + s.w * g_sc2[c4 + 3] + g_sh2[c4 + 3]);
    *(float4*)&out[(size_t)i * 4] = o;
}

// ---------------------------------------------------------------------------
extern "C" void kernel_launch(void* const* d_in, const int* in_sizes, int n_in,
                              void* d_out, int out_size) {
    const float* atom = (const float*)d_in[0];
    const float* nbr  = (const float*)d_in[1];
    const int*   idx  = (const int*)  d_in[2];
    const float* WK   = (const float*)d_in[3];
    const float* WQ   = (const float*)d_in[4];
    const float* WV   = (const float*)d_in[5];
    const float* WO   = (const float*)d_in[6];
    const float* Wfc  = (const float*)d_in[7];
    const float* bfc  = (const float*)d_in[8];
    const float* bn1g = (const float*)d_in[9];
    const float* bn1b = (const float*)d_in[10];
    const float* bn2g = (const float*)d_in[11];
    const float* bn2b = (const float*)d_in[12];
    float* out = (float*)d_out;

    int N = in_sizes[0] / ATOMF;

    cudaFuncSetAttribute(k_main, cudaFuncAttributeMaxDynamicSharedMemorySize, SMEM_MAIN_BYTES);
    cudaFuncSetAttribute(k_gate, cudaFuncAttributeMaxDynamicSharedMemorySize, SMEM_GATE_BYTES);

    k_prep<<<192, 256>>>(WK, WQ, WV, Wfc, WO);
    k_projT<<<(N + 47) / 48, 384>>>(atom, N);
    k_dummy<<<1, 32>>>(0);   // keep k_main as the 4th launch for ncu
    k_main<<<(N + APB - 1) / APB, BD, SMEM_MAIN_BYTES>>>(nbr, idx, N);
    k_bn1<<<128, 64>>>(bfc, bn1g, bn1b, 1.0 / ((double)N * MNBR));
    k_gate<<<(N + APB - 1) / APB, GBD, SMEM_GATE_BYTES>>>(bfc, N);
    k_bn2<<<1, 64>>>(bn2g, bn2b, 1.0 / (double)N);
    k_final<<<(N * ATOMF / 4 + 255) / 256, 256>>>(atom, out, N * ATOMF / 4);
}

// round 13
// speedup vs baseline: 1.0611x; 1.0611x over previous
#include <cuda_runtime.h>

// ---------------------------------------------------------------------------
#define NMAX   65536
#define MNBR   12
#define ATOMF  64
#define INF_   192
#define BD     384
#define GBD    256
#define APB    32      // atoms per block (8 groups of 4)

// ---------------------------------------------------------------------------
__device__ float g_Pself[NMAX * INF_];               // 48 MB
__device__ float g_Pnbr [NMAX * INF_];               // 48 MB
__device__ float g_att  [(size_t)NMAX * MNBR * 64];  // 201 MB (tf32-rounded)
__device__ float g_s    [NMAX * ATOMF];              // 16 MB
__device__ float g_WEt  [192 * 64];                  // edge weights, tf32
__device__ float g_Wall [384 * 64];                  // [self|nbr] proj weights, tf32
__device__ float g_Wfut [128 * 64];                  // fused W_fc@WO, tf32
__device__ float g_S    [64 * 64];
__device__ float g_svec [64];
__device__ float g_sum2[64], g_sq2[64];
__device__ float g_sc1[128], g_sh1[128], g_sc2[64], g_sh2[64];

// ---------------------------------------------------------------------------
__device__ __forceinline__ float tf32r(float x) {
    unsigned u; asm("cvt.rna.tf32.f32 %0, %1;" : "=r"(u) : "f"(x));
    return __uint_as_float(u);
}
__device__ __forceinline__ void mma8(float d[4], float a0, float a1, float a2, float a3,
                                     float b0, float b1) {
    unsigned A0 = __float_as_uint(a0), A1 = __float_as_uint(a1);
    unsigned A2 = __float_as_uint(a2), A3 = __float_as_uint(a3);
    unsigned B0 = __float_as_uint(b0), B1 = __float_as_uint(b1);
    asm volatile("mma.sync.aligned.m16n8k8.row.col.f32.tf32.tf32.f32 "
                 "{%0,%1,%2,%3}, {%4,%5,%6,%7}, {%8,%9}, {%0,%1,%2,%3};"
                 : "+f"(d[0]), "+f"(d[1]), "+f"(d[2]), "+f"(d[3])
                 : "r"(A0), "r"(A1), "r"(A2), "r"(A3), "r"(B0), "r"(B1));
}
__device__ __forceinline__ float sigf(float x) { return 1.f / (1.f + __expf(-x)); }
__device__ __forceinline__ float spf2(float x) {
    return fmaxf(x, 0.f) + __logf(1.f + __expf(-fabsf(x)));
}

__global__ void k_dummy(int x) { if (x == 12345) g_svec[63] += 0.f; }

// ---------------------------------------------------------------------------
// K_prep: tf32-round WEt, Wall; fuse W_fc@WO; zero stats. grid 192 x 256.
// ---------------------------------------------------------------------------
__global__ void k_prep(const float* __restrict__ WK, const float* __restrict__ WQ,
                       const float* __restrict__ WV, const float* __restrict__ Wfc,
                       const float* __restrict__ WO) {
    int t = threadIdx.x;
    if (blockIdx.x == 0 && t < 64) {
        g_sum2[t] = 0.f; g_sq2[t] = 0.f; g_svec[t] = 0.f;
    }
    int o = blockIdx.x * 256 + t;
    if (o < 12288) {
        int j = o >> 6, f = o & 63;
        const float* W = (j < 64) ? WK : ((j < 128) ? WQ : WV);
        g_WEt[o] = tf32r(W[(j & 63) * INF_ + 128 + f]);
    } else if (o < 36864) {
        int p = o - 12288;
        int j = p >> 6, f = p & 63;
        int half = (j >= 192);
        int jj = half ? j - 192 : j;
        const float* W = (jj < 64) ? WK : ((jj < 128) ? WQ : WV);
        g_Wall[p] = tf32r(W[(jj & 63) * INF_ + (half ? 64 : 0) + f]);
    } else if (o < 45056) {
        int p = o - 36864;
        int g = p >> 6, a = p & 63;
        const float* wr = Wfc + g * 256;
        float acc = 0.f;
        #pragma unroll 8
        for (int q = 0; q < 256; q++) acc += wr[q] * WO[q * 64 + a];
        g_Wfut[p] = tf32r(acc);
    } else if (o < 49152) {
        g_S[o - 45056] = 0.f;
    }
}

// ---------------------------------------------------------------------------
// K_projT: tensorized per-atom projections (single-term tf32).
// ---------------------------------------------------------------------------
__global__ __launch_bounds__(384, 2) void k_projT(const float* __restrict__ atom, int N) {
    __shared__ float sAT[48 * 68];
    int tid = threadIdx.x, wid = tid >> 5, lane = tid & 31;
    int qid = lane >> 2, tq = lane & 3;
    int n0 = blockIdx.x * 48;

    #pragma unroll
    for (int s = 0; s < 8; s++) {
        int i = tid + s * 384;
        int r = i >> 6, c = i & 63;
        int n = n0 + r;
        float v = (n < N) ? atom[(size_t)n * 64 + c] : 0.f;
        sAT[r * 68 + c] = tf32r(v);
    }
    __syncthreads();

    #pragma unroll
    for (int half = 0; half < 2; half++) {
        const float* Wsrc = g_Wall + (half * 192 + wid * 16) * 64;
        float aw[8][4];
        #pragma unroll
        for (int ks = 0; ks < 8; ks++) {
            int f0 = ks * 8 + tq;
            aw[ks][0] = Wsrc[qid * 64 + f0];
            aw[ks][1] = Wsrc[(qid + 8) * 64 + f0];
            aw[ks][2] = Wsrc[qid * 64 + f0 + 4];
            aw[ks][3] = Wsrc[(qid + 8) * 64 + f0 + 4];
        }
        float* ob = half ? g_Pnbr : g_Pself;
        #pragma unroll
        for (int nt = 0; nt < 6; nt++) {
            float d[4] = {0.f, 0.f, 0.f, 0.f};
            const float* ar = sAT + (8 * nt + qid) * 68;
            #pragma unroll
            for (int ks = 0; ks < 8; ks++)
                mma8(d, aw[ks][0], aw[ks][1], aw[ks][2], aw[ks][3],
                     ar[ks * 8 + tq], ar[ks * 8 + tq + 4]);
            int r0  = 8 * nt + 2 * tq;
            int ch0 = wid * 16 + qid;
            if (n0 + r0 < N) {
                ob[(size_t)(n0 + r0) * INF_ + ch0]     = d[0];
                ob[(size_t)(n0 + r0) * INF_ + ch0 + 8] = d[2];
            }
            if (n0 + r0 + 1 < N) {
                ob[(size_t)(n0 + r0 + 1) * INF_ + ch0]     = d[1];
                ob[(size_t)(n0 + r0 + 1) * INF_ + ch0 + 8] = d[3];
            }
        }
    }
}

// ---------------------------------------------------------------------------
// K_main: champion vectorized + double-buffered pipeline.
// ---------------------------------------------------------------------------
#define O_NF    0                 // 2 x 48x68 = 6528
#define O_KQV   6528              // 52 x 204 = 10608
#define O_LG    17136             // 4 x 272  = 1088
#define O_J     18224             // 2 x 48 ints
#define SMEM_FLOATS 18320
#define SMEM_MAIN_BYTES (SMEM_FLOATS * 4)

__global__ __launch_bounds__(BD, 2) void k_main(const float* __restrict__ nbr,
                                                const int*   __restrict__ idx,
                                                int N) {
    extern __shared__ float sm[];
    float* sNF0 = sm + O_NF;
    float* sNF1 = sm + O_NF + 3264;
    float* sKQV = sm + O_KQV;
    float* sLG  = sm + O_LG;
    int*   sJ0  = (int*)(sm + O_J);
    int*   sJ1  = sJ0 + 48;

    int tid  = threadIdx.x;
    int wid  = tid >> 5;
    int lane = tid & 31;
    int qid  = lane >> 2;
    int tq   = lane & 3;

    float aw[8][4];
    {
        int ch0 = 16 * wid + qid;
        #pragma unroll
        for (int ks = 0; ks < 8; ks++) {
            int f0 = ks * 8 + tq;
            aw[ks][0] = g_WEt[ch0 * 64 + f0];
            aw[ks][1] = g_WEt[(ch0 + 8) * 64 + f0];
            aw[ks][2] = g_WEt[ch0 * 64 + f0 + 4];
            aw[ks][3] = g_WEt[(ch0 + 8) * 64 + f0 + 4];
        }
    }

    // zero pad rows 48-51 of sKQV
    for (int i = tid; i < 4 * 204; i += BD) sKQV[48 * 204 + i] = 0.f;

    // prologue: NF(0) + sJ(0)
    {
        int n00 = blockIdx.x * APB;
        const float4* nb4 = (const float4*)(nbr + (size_t)n00 * 768);
        #pragma unroll
        for (int s = 0; s < 2; s++) {
            int v = tid + s * 384;          // 768 float4
            float4 x = nb4[v];
            x.x = tf32r(x.x); x.y = tf32r(x.y); x.z = tf32r(x.z); x.w = tf32r(x.w);
            *(float4*)&sNF0[(v >> 4) * 68 + (v & 15) * 4] = x;
        }
        if (tid < 48) sJ0[tid] = idx[n00 * MNBR + tid];
    }
    __syncthreads();

    for (int grp = 0; grp < 8; grp++) {
        int n0 = blockIdx.x * APB + grp * 4;
        if (n0 >= N) break;
        float* sNF  = (grp & 1) ? sNF1 : sNF0;
        int*   sJc  = (grp & 1) ? sJ1  : sJ0;
        float* sNFn = (grp & 1) ? sNF0 : sNF1;
        int*   sJn  = (grp & 1) ? sJ0  : sJ1;

        // ---- P1: vector gather -> sKQV (f32) ----
        #pragma unroll
        for (int s = 0; s < 6; s++) {
            int v  = tid + s * 384;          // 2304 float4 = 48 edges x 48
            int e  = v / 48;
            int c4 = (v - e * 48) * 4;
            int j  = sJc[e];
            int at = e / 12;
            float4 pn = *(const float4*)&g_Pnbr [(size_t)j * INF_ + c4];
            float4 ps = *(const float4*)&g_Pself[(size_t)(n0 + at) * INF_ + c4];
            float4 r;
            r.x = pn.x + ps.x; r.y = pn.y + ps.y;
            r.z = pn.z + ps.z; r.w = pn.w + ps.w;
            *(float4*)&sKQV[e * 204 + c4] = r;
        }
        __syncthreads();

        // ---- P2: edge MMA accumulating gather; epilogue tf32 ----
        {
            int ch0 = 16 * wid + qid;
            #pragma unroll
            for (int nt = 0; nt < 6; nt++) {
                int e0 = 8 * nt + 2 * tq;
                float d[4];
                d[0] = sKQV[e0 * 204 + ch0];
                d[1] = sKQV[(e0 + 1) * 204 + ch0];
                d[2] = sKQV[e0 * 204 + ch0 + 8];
                d[3] = sKQV[(e0 + 1) * 204 + ch0 + 8];
                const float* nrow = sNF + (8 * nt + qid) * 68;
                #pragma unroll
                for (int ks = 0; ks < 8; ks++) {
                    float b0 = nrow[ks * 8 + tq];
                    float b1 = nrow[ks * 8 + tq + 4];
                    mma8(d, aw[ks][0], aw[ks][1], aw[ks][2], aw[ks][3], b0, b1);
                }
                sKQV[e0 * 204 + ch0]           = tf32r(d[0]);
                sKQV[(e0 + 1) * 204 + ch0]     = tf32r(d[1]);
                sKQV[e0 * 204 + ch0 + 8]       = tf32r(d[2]);
                sKQV[(e0 + 1) * 204 + ch0 + 8] = tf32r(d[3]);
            }
        }
        __syncthreads();

        // ---- P3: logits+softmax (warps 0-3) | NF/idx prefetch (warps 4-11) ----
        if (wid < 4) {
            int a  = wid;
            int r0 = 12 * a;
            float d0[4] = {0.f, 0.f, 0.f, 0.f};
            float d1[4] = {0.f, 0.f, 0.f, 0.f};
            #pragma unroll
            for (int s = 0; s < 8; s++) {
                int f = 8 * s + tq;
                float a0 = sKQV[(r0 + qid) * 204 + f];
                float a1 = sKQV[(r0 + qid + 8) * 204 + f];
                float a2 = sKQV[(r0 + qid) * 204 + f + 4];
                float a3 = sKQV[(r0 + qid + 8) * 204 + f + 4];
                float b00 = sKQV[(r0 + qid) * 204 + 64 + f];
                float b01 = sKQV[(r0 + qid) * 204 + 64 + f + 4];
                float b10 = sKQV[(r0 + 8 + qid) * 204 + 64 + f];
                float b11 = sKQV[(r0 + 8 + qid) * 204 + 64 + f + 4];
                mma8(d0, a0, a1, a2, a3, b00, b01);
                mma8(d1, a0, a1, a2, a3, b10, b11);
            }
            float* lg = sLG + a * 272;
            bool colBad = (tq >= 2);
            {
                float l[4];
                l[0] = d0[0] * 0.125f; l[1] = d0[1] * 0.125f;
                l[2] = colBad ? -1e30f : d1[0] * 0.125f;
                l[3] = colBad ? -1e30f : d1[1] * 0.125f;
                float mx = fmaxf(fmaxf(l[0], l[1]), fmaxf(l[2], l[3]));
                mx = fmaxf(mx, __shfl_xor_sync(0xffffffffu, mx, 1));
                mx = fmaxf(mx, __shfl_xor_sync(0xffffffffu, mx, 2));
                float e0 = __expf(l[0] - mx), e1 = __expf(l[1] - mx);
                float e2 = __expf(l[2] - mx), e3 = __expf(l[3] - mx);
                float s = e0 + e1 + e2 + e3;
                s += __shfl_xor_sync(0xffffffffu, s, 1);
                s += __shfl_xor_sync(0xffffffffu, s, 2);
                float inv = 1.f / s;
                lg[qid * 17 + 2 * tq]         = tf32r(e0 * inv);
                lg[qid * 17 + 2 * tq + 1]     = tf32r(e1 * inv);
                lg[qid * 17 + 8 + 2 * tq]     = tf32r(e2 * inv);
                lg[qid * 17 + 8 + 2 * tq + 1] = tf32r(e3 * inv);
            }
            {
                bool rowOk = (qid < 4);
                float l[4];
                l[0] = d0[2] * 0.125f; l[1] = d0[3] * 0.125f;
                l[2] = colBad ? -1e30f : d1[2] * 0.125f;
                l[3] = colBad ? -1e30f : d1[3] * 0.125f;
                float mx = fmaxf(fmaxf(l[0], l[1]), fmaxf(l[2], l[3]));
                mx = fmaxf(mx, __shfl_xor_sync(0xffffffffu, mx, 1));
                mx = fmaxf(mx, __shfl_xor_sync(0xffffffffu, mx, 2));
                float e0 = __expf(l[0] - mx), e1 = __expf(l[1] - mx);
                float e2 = __expf(l[2] - mx), e3 = __expf(l[3] - mx);
                float s = e0 + e1 + e2 + e3;
                s += __shfl_xor_sync(0xffffffffu, s, 1);
                s += __shfl_xor_sync(0xffffffffu, s, 2);
                float inv = rowOk ? (1.f / s) : 0.f;
                lg[(qid + 8) * 17 + 2 * tq]         = tf32r(e0 * inv);
                lg[(qid + 8) * 17 + 2 * tq + 1]     = tf32r(e1 * inv);
                lg[(qid + 8) * 17 + 8 + 2 * tq]     = tf32r(e2 * inv);
                lg[(qid + 8) * 17 + 8 + 2 * tq + 1] = tf32r(e3 * inv);
            }
        } else if (grp < 7) {
            int n1 = n0 + 4;
            if (n1 < N) {
                int t2 = tid - 128;            // 0..255
                const float4* nb4 = (const float4*)(nbr + (size_t)n1 * 768);
                #pragma unroll
                for (int s = 0; s < 3; s++) {
                    int v = t2 + s * 256;      // 768 float4
                    float4 x = nb4[v];
                    x.x = tf32r(x.x); x.y = tf32r(x.y); x.z = tf32r(x.z); x.w = tf32r(x.w);
                    *(float4*)&sNFn[(v >> 4) * 68 + (v & 15) * 4] = x;
                }
                if (t2 < 48) sJn[t2] = idx[n1 * MNBR + t2];
            }
        }
        __syncthreads();

        // ---- P5: attn = W @ V MMA -> direct STG to g_att ----
        if (wid < 8) {
            int a = wid >> 1;
            int ntb = (wid & 1) * 4;
            const float* lg = sLG + a * 272;
            float af[2][4];
            #pragma unroll
            for (int s = 0; s < 2; s++) {
                int k = 8 * s + tq;
                af[s][0] = lg[qid * 17 + k];
                af[s][1] = lg[(qid + 8) * 17 + k];
                af[s][2] = lg[qid * 17 + k + 4];
                af[s][3] = lg[(qid + 8) * 17 + k + 4];
            }
            float* go = g_att + (size_t)n0 * 768 + 12 * a * 64;
            #pragma unroll
            for (int j = 0; j < 4; j++) {
                int nt = ntb + j;
                float d[4] = {0.f, 0.f, 0.f, 0.f};
                #pragma unroll
                for (int s = 0; s < 2; s++) {
                    int kr = 12 * a + 8 * s + tq;
                    float b0 = sKQV[kr * 204 + 128 + 8 * nt + qid];
                    float b1 = sKQV[(kr + 4) * 204 + 128 + 8 * nt + qid];
                    mma8(d, af[s][0], af[s][1], af[s][2], af[s][3], b0, b1);
                }
                int col = 8 * nt + 2 * tq;
                float2 w0 = {tf32r(d[0]), tf32r(d[1])};
                *(float2*)&go[qid * 64 + col] = w0;
                if (qid < 4) {
                    float2 w1 = {tf32r(d[2]), tf32r(d[3])};
                    *(float2*)&go[(qid + 8) * 64 + col] = w1;
                }
            }
        }
        __syncthreads();   // sKQV reused next group
    }
}

// ---------------------------------------------------------------------------
// K_stats: S = att^T @ att + svec, vectorized loads.
// FIXED: svec accumulated per-channel (bucket = (tid&15)*4 + k), not tid&63.
// ---------------------------------------------------------------------------
__global__ __launch_bounds__(256, 4) void k_stats(int nChunks) {
    __shared__ float sA[128 * 68];
    __shared__ float ssv[64];
    int tid  = threadIdx.x;
    int wid  = tid >> 5;
    int lane = tid & 31;
    int qid  = lane >> 2;
    int tq   = lane & 3;
    int mt   = wid >> 1;
    int ntb  = (wid & 1) * 4;

    if (tid < 64) ssv[tid] = 0.f;
    float sacc[4][4];
    #pragma unroll
    for (int i = 0; i < 4; i++)
        #pragma unroll
        for (int j = 0; j < 4; j++) sacc[i][j] = 0.f;
    float sv[4] = {0.f, 0.f, 0.f, 0.f};

    for (int ch = blockIdx.x; ch < nChunks; ch += gridDim.x) {
        const float4* ai4 = (const float4*)(g_att + (size_t)ch * 8192);
        __syncthreads();
        #pragma unroll
        for (int s = 0; s < 8; s++) {
            int v = tid + s * 256;           // 2048 float4; channel base (v&15)*4 == (tid&15)*4
            float4 x = ai4[v];
            *(float4*)&sA[(v >> 4) * 68 + (v & 15) * 4] = x;
            sv[0] += x.x; sv[1] += x.y; sv[2] += x.z; sv[3] += x.w;
        }
        __syncthreads();
        #pragma unroll
        for (int ks = 0; ks < 16; ks++) {
            int kr = 8 * ks + tq;
            float a0 = sA[kr * 68 + 16 * mt + qid];
            float a1 = sA[kr * 68 + 16 * mt + qid + 8];
            float a2 = sA[(kr + 4) * 68 + 16 * mt + qid];
            float a3 = sA[(kr + 4) * 68 + 16 * mt + qid + 8];
            #pragma unroll
            for (int j = 0; j < 4; j++) {
                int nt = ntb + j;
                float b0 = sA[kr * 68 + 8 * nt + qid];
                float b1 = sA[(kr + 4) * 68 + 8 * nt + qid];
                mma8(sacc[j], a0, a1, a2, a3, b0, b1);
            }
        }
    }
    {
        int c4 = (tid & 15) * 4;
        atomicAdd(&ssv[c4],     sv[0]);
        atomicAdd(&ssv[c4 + 1], sv[1]);
        atomicAdd(&ssv[c4 + 2], sv[2]);
        atomicAdd(&ssv[c4 + 3], sv[3]);
    }
    #pragma unroll
    for (int j = 0; j < 4; j++) {
        int c1 = 16 * mt + qid;
        int c2 = 8 * (ntb + j) + 2 * tq;
        atomicAdd(&g_S[c1 * 64 + c2],           sacc[j][0]);
        atomicAdd(&g_S[c1 * 64 + c2 + 1],       sacc[j][1]);
        atomicAdd(&g_S[(c1 + 8) * 64 + c2],     sacc[j][2]);
        atomicAdd(&g_S[(c1 + 8) * 64 + c2 + 1], sacc[j][3]);
    }
    __syncthreads();
    if (tid < 64) atomicAdd(&g_svec[tid], ssv[tid]);
}

// ---------------------------------------------------------------------------
// K_bn1: moment trick, double-precision reduction.
// ---------------------------------------------------------------------------
__global__ void k_bn1(const float* __restrict__ bfc, const float* __restrict__ g1,
                      const float* __restrict__ b1, double invCnt) {
    __shared__ float sS[64 * 65];
    __shared__ float sw[64];
    __shared__ double red[4];
    int g = blockIdx.x;
    int i = threadIdx.x;
    sw[i] = g_Wfut[g * 64 + i];
    for (int l = i; l < 4096; l += 64)
        sS[(l >> 6) * 65 + (l & 63)] = g_S[l];
    __syncthreads();
    double y = 0.0;
    #pragma unroll 8
    for (int j = 0; j < 64; j++) y += (double)sS[i * 65 + j] * (double)sw[j];
    y *= (double)sw[i];
    double p = (double)sw[i] * (double)g_svec[i];
    #pragma unroll
    for (int off = 16; off > 0; off >>= 1) {
        y += __shfl_xor_sync(0xffffffffu, y, off);
        p += __shfl_xor_sync(0xffffffffu, p, off);
    }
    if ((i & 31) == 0) { red[(i >> 5) * 2] = y; red[(i >> 5) * 2 + 1] = p; }
    __syncthreads();
    if (i == 0) {
        double quad = red[0] + red[2];
        double lin  = red[1] + red[3];
        double b    = (double)bfc[g];
        double mean = lin * invCnt + b;
        double ex2  = (quad + 2.0 * b * lin) * invCnt + b * b;
        double var  = ex2 - mean * mean;
        double sc   = (double)g1[g] / sqrt(var + 1e-5);
        g_sc1[g] = (float)sc;
        g_sh1[g] = (float)((double)b1[g] - mean * sc);
    }
}

// ---------------------------------------------------------------------------
// K_gate: register-resident gated + activation + per-atom reduction.
// ---------------------------------------------------------------------------
#define SMEM_GATE_FLOATS (48 * 68)
#define SMEM_GATE_BYTES (SMEM_GATE_FLOATS * 4)

__global__ __launch_bounds__(GBD, 3) void k_gate(const float* __restrict__ bfc, int N) {
    extern __shared__ float sm[];
    float* sA = sm;

    int tid  = threadIdx.x;
    int wid  = tid >> 5;
    int lane = tid & 31;
    int qid  = lane >> 2;
    int tq   = lane & 3;

    float bwf[8][2], bwh[8][2];
    float bbf[2], bbh[2];
    {
        int rf = wid * 8 + qid;
        int rh = 64 + wid * 8 + qid;
        float scf = g_sc1[rf], sch = g_sc1[rh];
        #pragma unroll
        for (int ks = 0; ks < 8; ks++) {
            bwf[ks][0] = tf32r(g_Wfut[rf * 64 + ks * 8 + tq] * scf);
            bwf[ks][1] = tf32r(g_Wfut[rf * 64 + ks * 8 + tq + 4] * scf);
            bwh[ks][0] = tf32r(g_Wfut[rh * 64 + ks * 8 + tq] * sch);
            bwh[ks][1] = tf32r(g_Wfut[rh * 64 + ks * 8 + tq + 4] * sch);
        }
        int cf = wid * 8 + 2 * tq;
        bbf[0] = bfc[cf]          * g_sc1[cf]          + g_sh1[cf];
        bbf[1] = bfc[cf + 1]      * g_sc1[cf + 1]      + g_sh1[cf + 1];
        bbh[0] = bfc[64 + cf]     * g_sc1[64 + cf]     + g_sh1[64 + cf];
        bbh[1] = bfc[64 + cf + 1] * g_sc1[64 + cf + 1] + g_sh1[64 + cf + 1];
    }
    float ls0 = 0.f, ls1 = 0.f, lq0 = 0.f, lq1 = 0.f;

    for (int grp = 0; grp < 8; grp++) {
        int n0 = blockIdx.x * APB + grp * 4;
        if (n0 >= N) break;

        const float4* ai4 = (const float4*)(g_att + (size_t)n0 * 768);
        #pragma unroll
        for (int s = 0; s < 3; s++) {
            int v = tid + s * GBD;           // 768 float4
            float4 x = ai4[v];
            *(float4*)&sA[(v >> 4) * 68 + (v & 15) * 4] = x;
        }
        __syncthreads();

        float acc[4][2];
        #pragma unroll
        for (int a = 0; a < 4; a++) { acc[a][0] = 0.f; acc[a][1] = 0.f; }

        #pragma unroll
        for (int mt = 0; mt < 3; mt++) {
            int r0 = 16 * mt + qid;
            float a[8][4];
            #pragma unroll
            for (int ks = 0; ks < 8; ks++) {
                int c0 = ks * 8 + tq;
                a[ks][0] = sA[r0 * 68 + c0];
                a[ks][1] = sA[(r0 + 8) * 68 + c0];
                a[ks][2] = sA[r0 * 68 + c0 + 4];
                a[ks][3] = sA[(r0 + 8) * 68 + c0 + 4];
            }
            float f[4] = {0.f, 0.f, 0.f, 0.f};
            float h[4] = {0.f, 0.f, 0.f, 0.f};
            #pragma unroll
            for (int ks = 0; ks < 8; ks++) {
                mma8(f, a[ks][0], a[ks][1], a[ks][2], a[ks][3], bwf[ks][0], bwf[ks][1]);
                mma8(h, a[ks][0], a[ks][1], a[ks][2], a[ks][3], bwh[ks][0], bwh[ks][1]);
            }
            float v0 = sigf(f[0] + bbf[0]) * spf2(h[0] + bbh[0]);
            float v1 = sigf(f[1] + bbf[1]) * spf2(h[1] + bbh[1]);
            float v2 = sigf(f[2] + bbf[0]) * spf2(h[2] + bbh[0]);
            float v3 = sigf(f[3] + bbf[1]) * spf2(h[3] + bbh[1]);
            if (mt == 0) {
                acc[0][0] += v0; acc[0][1] += v1;
                if (qid < 4) { acc[0][0] += v2; acc[0][1] += v3; }
                else         { acc[1][0] += v2; acc[1][1] += v3; }
            } else if (mt == 1) {
                acc[1][0] += v0; acc[1][1] += v1;
                acc[2][0] += v2; acc[2][1] += v3;
            } else {
                if (qid < 4) { acc[2][0] += v0; acc[2][1] += v1; }
                else         { acc[3][0] += v0; acc[3][1] += v1; }
                acc[3][0] += v2; acc[3][1] += v3;
            }
        }

        #pragma unroll
        for (int a = 0; a < 4; a++) {
            #pragma unroll
            for (int c = 0; c < 2; c++) {
                float v = acc[a][c];
                v += __shfl_xor_sync(0xffffffffu, v, 4);
                v += __shfl_xor_sync(0xffffffffu, v, 8);
                v += __shfl_xor_sync(0xffffffffu, v, 16);
                acc[a][c] = v;
            }
        }
        if (lane < 4) {
            int col = wid * 8 + 2 * lane;
            #pragma unroll
            for (int a = 0; a < 4; a++) {
                g_s[(size_t)(n0 + a) * 64 + col]     = acc[a][0];
                g_s[(size_t)(n0 + a) * 64 + col + 1] = acc[a][1];
                ls0 += acc[a][0]; lq0 += acc[a][0] * acc[a][0];
                ls1 += acc[a][1]; lq1 += acc[a][1] * acc[a][1];
            }
        }
        __syncthreads();
    }
    if (lane < 4) {
        int col = wid * 8 + 2 * lane;
        atomicAdd(&g_sum2[col],     ls0);
        atomicAdd(&g_sq2[col],      lq0);
        atomicAdd(&g_sum2[col + 1], ls1);
        atomicAdd(&g_sq2[col + 1],  lq1);
    }
}

// ---------------------------------------------------------------------------
// K_bn2: double-precision var computation.
// ---------------------------------------------------------------------------
__global__ void k_bn2(const float* __restrict__ g2, const float* __restrict__ b2, double invCnt) {
    int t = threadIdx.x;
    double m = (double)g_sum2[t] * invCnt;
    double v = (double)g_sq2[t] * invCnt - m * m;
    double sc = (double)g2[t] / sqrt(v + 1e-5);
    g_sc2[t] = (float)sc;
    g_sh2[t] = (float)((double)b2[t] - m * sc);
}

__global__ void k_final(const float* __restrict__ atom, float* __restrict__ out, int nVec) {
    int i = blockIdx.x * blockDim.x + threadIdx.x;
    if (i >= nVec) return;
    int c4 = (i & 15) * 4;
    float4 a = *(const float4*)&atom[(size_t)i * 4];
    float4 s = *(const float4*)&g_s[(size_t)i * 4];
    float4 o;
    o.x = spf2(a.x + s.x * g_sc2[c4]     + g_sh2[c4]);
    o.y = spf2(a.y + s.y * g_sc2[c4 + 1] + g_sh2[c4 + 1]);
    o.z = spf2(a.z + s.z * g_sc2[c4 + 2] + g_sh2[c4 + 2]);
    o.w = spf2(a.w + s.w * g_sc2[c4 + 3] + g_sh2[c4 + 3]);
    *(float4*)&out[(size_t)i * 4] = o;
}

// ---------------------------------------------------------------------------
extern "C" void kernel_launch(void* const* d_in, const int* in_sizes, int n_in,
                              void* d_out, int out_size) {
    const float* atom = (const float*)d_in[0];
    const float* nbr  = (const float*)d_in[1];
    const int*   idx  = (const int*)  d_in[2];
    const float* WK   = (const float*)d_in[3];
    const float* WQ   = (const float*)d_in[4];
    const float* WV   = (const float*)d_in[5];
    const float* WO   = (const float*)d_in[6];
    const float* Wfc  = (const float*)d_in[7];
    const float* bfc  = (const float*)d_in[8];
    const float* bn1g = (const float*)d_in[9];
    const float* bn1b = (const float*)d_in[10];
    const float* bn2g = (const float*)d_in[11];
    const float* bn2b = (const float*)d_in[12];
    float* out = (float*)d_out;

    int N = in_sizes[0] / ATOMF;
    int nChunks = (N * MNBR * ATOMF) / 8192;

    cudaFuncSetAttribute(k_main, cudaFuncAttributeMaxDynamicSharedMemorySize, SMEM_MAIN_BYTES);
    cudaFuncSetAttribute(k_gate, cudaFuncAttributeMaxDynamicSharedMemorySize, SMEM_GATE_BYTES);

    k_prep<<<192, 256>>>(WK, WQ, WV, Wfc, WO);
    k_projT<<<(N + 47) / 48, 384>>>(atom, N);
    k_dummy<<<1, 32>>>(0);   // keep k_main as the 4th launch for ncu
    k_main<<<(N + APB - 1) / APB, BD, SMEM_MAIN_BYTES>>>(nbr, idx, N);
    k_stats<<<1024, 256>>>(nChunks);
    k_bn1<<<128, 64>>>(bfc, bn1g, bn1b, 1.0 / ((double)N * MNBR));
    k_gate<<<(N + APB - 1) / APB, GBD, SMEM_GATE_BYTES>>>(bfc, N);
    k_bn2<<<1, 64>>>(bn2g, bn2b, 1.0 / (double)N);
    k_final<<<(N * ATOMF / 4 + 255) / 256, 256>>>(atom, out, N * ATOMF / 4);
}

// round 14
// speedup vs baseline: 1.1356x; 1.0703x over previous
#include <cuda_runtime.h>

// ---------------------------------------------------------------------------
#define NMAX   65536
#define MNBR   12
#define ATOMF  64
#define INF_   192
#define BD     384
#define GBD    256
#define APB    32      // atoms per block (8 groups of 4)

// ---------------------------------------------------------------------------
__device__ float g_Pself[NMAX * INF_];               // 48 MB
__device__ float g_Pnbr [NMAX * INF_];               // 48 MB
__device__ float g_att  [(size_t)NMAX * MNBR * 64];  // 201 MB (tf32-rounded)
__device__ float g_s    [NMAX * ATOMF];              // 16 MB
__device__ float g_WEt  [192 * 64];                  // edge weights, tf32
__device__ float g_Wall [384 * 64];                  // [self|nbr] proj weights, tf32
__device__ float g_Wfut [128 * 64];                  // fused W_fc@WO, tf32
__device__ float g_S    [64 * 64];
__device__ float g_svec [64];
__device__ float g_sum2[64], g_sq2[64];
__device__ float g_sc1[128], g_sh1[128], g_sc2[64], g_sh2[64];

// ---------------------------------------------------------------------------
__device__ __forceinline__ float tf32r(float x) {
    unsigned u; asm("cvt.rna.tf32.f32 %0, %1;" : "=r"(u) : "f"(x));
    return __uint_as_float(u);
}
__device__ __forceinline__ void mma8(float d[4], float a0, float a1, float a2, float a3,
                                     float b0, float b1) {
    unsigned A0 = __float_as_uint(a0), A1 = __float_as_uint(a1);
    unsigned A2 = __float_as_uint(a2), A3 = __float_as_uint(a3);
    unsigned B0 = __float_as_uint(b0), B1 = __float_as_uint(b1);
    asm volatile("mma.sync.aligned.m16n8k8.row.col.f32.tf32.tf32.f32 "
                 "{%0,%1,%2,%3}, {%4,%5,%6,%7}, {%8,%9}, {%0,%1,%2,%3};"
                 : "+f"(d[0]), "+f"(d[1]), "+f"(d[2]), "+f"(d[3])
                 : "r"(A0), "r"(A1), "r"(A2), "r"(A3), "r"(B0), "r"(B1));
}
// sigmoid via single-MUFU tanh.approx: sig(x) = 0.5*tanh(x/2) + 0.5
__device__ __forceinline__ float sigf(float x) {
    float t;
    asm("tanh.approx.f32 %0, %1;" : "=f"(t) : "f"(0.5f * x));
    return fmaf(0.5f, t, 0.5f);
}
__device__ __forceinline__ float spf2(float x) {
    return fmaxf(x, 0.f) + __logf(1.f + __expf(-fabsf(x)));
}

// ---------------------------------------------------------------------------
// K_prep: tf32-round WEt, Wall; fuse W_fc@WO; zero stats. grid 192 x 256.
// ---------------------------------------------------------------------------
__global__ void k_prep(const float* __restrict__ WK, const float* __restrict__ WQ,
                       const float* __restrict__ WV, const float* __restrict__ Wfc,
                       const float* __restrict__ WO) {
    int t = threadIdx.x;
    if (blockIdx.x == 0 && t < 64) {
        g_sum2[t] = 0.f; g_sq2[t] = 0.f; g_svec[t] = 0.f;
    }
    int o = blockIdx.x * 256 + t;
    if (o < 12288) {
        int j = o >> 6, f = o & 63;
        const float* W = (j < 64) ? WK : ((j < 128) ? WQ : WV);
        g_WEt[o] = tf32r(W[(j & 63) * INF_ + 128 + f]);
    } else if (o < 36864) {
        int p = o - 12288;
        int j = p >> 6, f = p & 63;
        int half = (j >= 192);
        int jj = half ? j - 192 : j;
        const float* W = (jj < 64) ? WK : ((jj < 128) ? WQ : WV);
        g_Wall[p] = tf32r(W[(jj & 63) * INF_ + (half ? 64 : 0) + f]);
    } else if (o < 45056) {
        int p = o - 36864;
        int g = p >> 6, a = p & 63;
        const float* wr = Wfc + g * 256;
        float acc = 0.f;
        #pragma unroll 8
        for (int q = 0; q < 256; q++) acc += wr[q] * WO[q * 64 + a];
        g_Wfut[p] = tf32r(acc);
    } else if (o < 49152) {
        g_S[o - 45056] = 0.f;
    }
}

// ---------------------------------------------------------------------------
// K_projT: tensorized per-atom projections (single-term tf32).
// ---------------------------------------------------------------------------
__global__ __launch_bounds__(384, 2) void k_projT(const float* __restrict__ atom, int N) {
    __shared__ float sAT[48 * 68];
    int tid = threadIdx.x, wid = tid >> 5, lane = tid & 31;
    int qid = lane >> 2, tq = lane & 3;
    int n0 = blockIdx.x * 48;

    #pragma unroll
    for (int s = 0; s < 8; s++) {
        int i = tid + s * 384;
        int r = i >> 6, c = i & 63;
        int n = n0 + r;
        float v = (n < N) ? atom[(size_t)n * 64 + c] : 0.f;
        sAT[r * 68 + c] = tf32r(v);
    }
    __syncthreads();

    #pragma unroll
    for (int half = 0; half < 2; half++) {
        const float* Wsrc = g_Wall + (half * 192 + wid * 16) * 64;
        float aw[8][4];
        #pragma unroll
        for (int ks = 0; ks < 8; ks++) {
            int f0 = ks * 8 + tq;
            aw[ks][0] = Wsrc[qid * 64 + f0];
            aw[ks][1] = Wsrc[(qid + 8) * 64 + f0];
            aw[ks][2] = Wsrc[qid * 64 + f0 + 4];
            aw[ks][3] = Wsrc[(qid + 8) * 64 + f0 + 4];
        }
        float* ob = half ? g_Pnbr : g_Pself;
        #pragma unroll
        for (int nt = 0; nt < 6; nt++) {
            float d[4] = {0.f, 0.f, 0.f, 0.f};
            const float* ar = sAT + (8 * nt + qid) * 68;
            #pragma unroll
            for (int ks = 0; ks < 8; ks++)
                mma8(d, aw[ks][0], aw[ks][1], aw[ks][2], aw[ks][3],
                     ar[ks * 8 + tq], ar[ks * 8 + tq + 4]);
            int r0  = 8 * nt + 2 * tq;
            int ch0 = wid * 16 + qid;
            if (n0 + r0 < N) {
                ob[(size_t)(n0 + r0) * INF_ + ch0]     = d[0];
                ob[(size_t)(n0 + r0) * INF_ + ch0 + 8] = d[2];
            }
            if (n0 + r0 + 1 < N) {
                ob[(size_t)(n0 + r0 + 1) * INF_ + ch0]     = d[1];
                ob[(size_t)(n0 + r0 + 1) * INF_ + ch0 + 8] = d[3];
            }
        }
    }
}

// ---------------------------------------------------------------------------
// K_main: champion vectorized + double-buffered pipeline; streaming hints.
// ---------------------------------------------------------------------------
#define O_NF    0                 // 2 x 48x68 = 6528
#define O_KQV   6528              // 52 x 204 = 10608
#define O_LG    17136             // 4 x 272  = 1088
#define O_J     18224             // 2 x 48 ints
#define SMEM_FLOATS 18320
#define SMEM_MAIN_BYTES (SMEM_FLOATS * 4)

__global__ __launch_bounds__(BD, 2) void k_main(const float* __restrict__ nbr,
                                                const int*   __restrict__ idx,
                                                int N) {
    extern __shared__ float sm[];
    float* sNF0 = sm + O_NF;
    float* sNF1 = sm + O_NF + 3264;
    float* sKQV = sm + O_KQV;
    float* sLG  = sm + O_LG;
    int*   sJ0  = (int*)(sm + O_J);
    int*   sJ1  = sJ0 + 48;

    int tid  = threadIdx.x;
    int wid  = tid >> 5;
    int lane = tid & 31;
    int qid  = lane >> 2;
    int tq   = lane & 3;

    float aw[8][4];
    {
        int ch0 = 16 * wid + qid;
        #pragma unroll
        for (int ks = 0; ks < 8; ks++) {
            int f0 = ks * 8 + tq;
            aw[ks][0] = g_WEt[ch0 * 64 + f0];
            aw[ks][1] = g_WEt[(ch0 + 8) * 64 + f0];
            aw[ks][2] = g_WEt[ch0 * 64 + f0 + 4];
            aw[ks][3] = g_WEt[(ch0 + 8) * 64 + f0 + 4];
        }
    }

    // zero pad rows 48-51 of sKQV
    for (int i = tid; i < 4 * 204; i += BD) sKQV[48 * 204 + i] = 0.f;

    // prologue: NF(0) + sJ(0)
    {
        int n00 = blockIdx.x * APB;
        const float4* nb4 = (const float4*)(nbr + (size_t)n00 * 768);
        #pragma unroll
        for (int s = 0; s < 2; s++) {
            int v = tid + s * 384;          // 768 float4
            float4 x = __ldcs(&nb4[v]);
            x.x = tf32r(x.x); x.y = tf32r(x.y); x.z = tf32r(x.z); x.w = tf32r(x.w);
            *(float4*)&sNF0[(v >> 4) * 68 + (v & 15) * 4] = x;
        }
        if (tid < 48) sJ0[tid] = idx[n00 * MNBR + tid];
    }
    __syncthreads();

    for (int grp = 0; grp < 8; grp++) {
        int n0 = blockIdx.x * APB + grp * 4;
        if (n0 >= N) break;
        float* sNF  = (grp & 1) ? sNF1 : sNF0;
        int*   sJc  = (grp & 1) ? sJ1  : sJ0;
        float* sNFn = (grp & 1) ? sNF0 : sNF1;
        int*   sJn  = (grp & 1) ? sJ0  : sJ1;

        // ---- P1: vector gather -> sKQV (f32) ----
        #pragma unroll
        for (int s = 0; s < 6; s++) {
            int v  = tid + s * 384;          // 2304 float4 = 48 edges x 48
            int e  = v / 48;
            int c4 = (v - e * 48) * 4;
            int j  = sJc[e];
            int at = e / 12;
            float4 pn = *(const float4*)&g_Pnbr [(size_t)j * INF_ + c4];
            float4 ps = *(const float4*)&g_Pself[(size_t)(n0 + at) * INF_ + c4];
            float4 r;
            r.x = pn.x + ps.x; r.y = pn.y + ps.y;
            r.z = pn.z + ps.z; r.w = pn.w + ps.w;
            *(float4*)&sKQV[e * 204 + c4] = r;
        }
        __syncthreads();

        // ---- P2: edge MMA accumulating gather; epilogue tf32 ----
        {
            int ch0 = 16 * wid + qid;
            #pragma unroll
            for (int nt = 0; nt < 6; nt++) {
                int e0 = 8 * nt + 2 * tq;
                float d[4];
                d[0] = sKQV[e0 * 204 + ch0];
                d[1] = sKQV[(e0 + 1) * 204 + ch0];
                d[2] = sKQV[e0 * 204 + ch0 + 8];
                d[3] = sKQV[(e0 + 1) * 204 + ch0 + 8];
                const float* nrow = sNF + (8 * nt + qid) * 68;
                #pragma unroll
                for (int ks = 0; ks < 8; ks++) {
                    float b0 = nrow[ks * 8 + tq];
                    float b1 = nrow[ks * 8 + tq + 4];
                    mma8(d, aw[ks][0], aw[ks][1], aw[ks][2], aw[ks][3], b0, b1);
                }
                sKQV[e0 * 204 + ch0]           = tf32r(d[0]);
                sKQV[(e0 + 1) * 204 + ch0]     = tf32r(d[1]);
                sKQV[e0 * 204 + ch0 + 8]       = tf32r(d[2]);
                sKQV[(e0 + 1) * 204 + ch0 + 8] = tf32r(d[3]);
            }
        }
        __syncthreads();

        // ---- P3: logits+softmax (warps 0-3) | NF/idx prefetch (warps 4-11) ----
        if (wid < 4) {
            int a  = wid;
            int r0 = 12 * a;
            float d0[4] = {0.f, 0.f, 0.f, 0.f};
            float d1[4] = {0.f, 0.f, 0.f, 0.f};
            #pragma unroll
            for (int s = 0; s < 8; s++) {
                int f = 8 * s + tq;
                float a0 = sKQV[(r0 + qid) * 204 + f];
                float a1 = sKQV[(r0 + qid + 8) * 204 + f];
                float a2 = sKQV[(r0 + qid) * 204 + f + 4];
                float a3 = sKQV[(r0 + qid + 8) * 204 + f + 4];
                float b00 = sKQV[(r0 + qid) * 204 + 64 + f];
                float b01 = sKQV[(r0 + qid) * 204 + 64 + f + 4];
                float b10 = sKQV[(r0 + 8 + qid) * 204 + 64 + f];
                float b11 = sKQV[(r0 + 8 + qid) * 204 + 64 + f + 4];
                mma8(d0, a0, a1, a2, a3, b00, b01);
                mma8(d1, a0, a1, a2, a3, b10, b11);
            }
            float* lg = sLG + a * 272;
            bool colBad = (tq >= 2);
            {
                float l[4];
                l[0] = d0[0] * 0.125f; l[1] = d0[1] * 0.125f;
                l[2] = colBad ? -1e30f : d1[0] * 0.125f;
                l[3] = colBad ? -1e30f : d1[1] * 0.125f;
                float mx = fmaxf(fmaxf(l[0], l[1]), fmaxf(l[2], l[3]));
                mx = fmaxf(mx, __shfl_xor_sync(0xffffffffu, mx, 1));
                mx = fmaxf(mx, __shfl_xor_sync(0xffffffffu, mx, 2));
                float e0 = __expf(l[0] - mx), e1 = __expf(l[1] - mx);
                float e2 = __expf(l[2] - mx), e3 = __expf(l[3] - mx);
                float s = e0 + e1 + e2 + e3;
                s += __shfl_xor_sync(0xffffffffu, s, 1);
                s += __shfl_xor_sync(0xffffffffu, s, 2);
                float inv = 1.f / s;
                lg[qid * 17 + 2 * tq]         = tf32r(e0 * inv);
                lg[qid * 17 + 2 * tq + 1]     = tf32r(e1 * inv);
                lg[qid * 17 + 8 + 2 * tq]     = tf32r(e2 * inv);
                lg[qid * 17 + 8 + 2 * tq + 1] = tf32r(e3 * inv);
            }
            {
                bool rowOk = (qid < 4);
                float l[4];
                l[0] = d0[2] * 0.125f; l[1] = d0[3] * 0.125f;
                l[2] = colBad ? -1e30f : d1[2] * 0.125f;
                l[3] = colBad ? -1e30f : d1[3] * 0.125f;
                float mx = fmaxf(fmaxf(l[0], l[1]), fmaxf(l[2], l[3]));
                mx = fmaxf(mx, __shfl_xor_sync(0xffffffffu, mx, 1));
                mx = fmaxf(mx, __shfl_xor_sync(0xffffffffu, mx, 2));
                float e0 = __expf(l[0] - mx), e1 = __expf(l[1] - mx);
                float e2 = __expf(l[2] - mx), e3 = __expf(l[3] - mx);
                float s = e0 + e1 + e2 + e3;
                s += __shfl_xor_sync(0xffffffffu, s, 1);
                s += __shfl_xor_sync(0xffffffffu, s, 2);
                float inv = rowOk ? (1.f / s) : 0.f;
                lg[(qid + 8) * 17 + 2 * tq]         = tf32r(e0 * inv);
                lg[(qid + 8) * 17 + 2 * tq + 1]     = tf32r(e1 * inv);
                lg[(qid + 8) * 17 + 8 + 2 * tq]     = tf32r(e2 * inv);
                lg[(qid + 8) * 17 + 8 + 2 * tq + 1] = tf32r(e3 * inv);
            }
        } else if (grp < 7) {
            int n1 = n0 + 4;
            if (n1 < N) {
                int t2 = tid - 128;            // 0..255
                const float4* nb4 = (const float4*)(nbr + (size_t)n1 * 768);
                #pragma unroll
                for (int s = 0; s < 3; s++) {
                    int v = t2 + s * 256;      // 768 float4
                    float4 x = __ldcs(&nb4[v]);
                    x.x = tf32r(x.x); x.y = tf32r(x.y); x.z = tf32r(x.z); x.w = tf32r(x.w);
                    *(float4*)&sNFn[(v >> 4) * 68 + (v & 15) * 4] = x;
                }
                if (t2 < 48) sJn[t2] = idx[n1 * MNBR + t2];
            }
        }
        __syncthreads();

        // ---- P5: attn = W @ V MMA -> streaming STG to g_att ----
        if (wid < 8) {
            int a = wid >> 1;
            int ntb = (wid & 1) * 4;
            const float* lg = sLG + a * 272;
            float af[2][4];
            #pragma unroll
            for (int s = 0; s < 2; s++) {
                int k = 8 * s + tq;
                af[s][0] = lg[qid * 17 + k];
                af[s][1] = lg[(qid + 8) * 17 + k];
                af[s][2] = lg[qid * 17 + k + 4];
                af[s][3] = lg[(qid + 8) * 17 + k + 4];
            }
            float* go = g_att + (size_t)n0 * 768 + 12 * a * 64;
            #pragma unroll
            for (int j = 0; j < 4; j++) {
                int nt = ntb + j;
                float d[4] = {0.f, 0.f, 0.f, 0.f};
                #pragma unroll
                for (int s = 0; s < 2; s++) {
                    int kr = 12 * a + 8 * s + tq;
                    float b0 = sKQV[kr * 204 + 128 + 8 * nt + qid];
                    float b1 = sKQV[(kr + 4) * 204 + 128 + 8 * nt + qid];
                    mma8(d, af[s][0], af[s][1], af[s][2], af[s][3], b0, b1);
                }
                int col = 8 * nt + 2 * tq;
                float2 w0 = {tf32r(d[0]), tf32r(d[1])};
                __stcs((float2*)&go[qid * 64 + col], w0);
                if (qid < 4) {
                    float2 w1 = {tf32r(d[2]), tf32r(d[3])};
                    __stcs((float2*)&go[(qid + 8) * 64 + col], w1);
                }
            }
        }
        __syncthreads();   // sKQV reused next group
    }
}

// ---------------------------------------------------------------------------
// K_stats: S = att^T @ att + svec (per-channel), streaming loads.
// ---------------------------------------------------------------------------
__global__ __launch_bounds__(256, 4) void k_stats(int nChunks) {
    __shared__ float sA[128 * 68];
    __shared__ float ssv[64];
    int tid  = threadIdx.x;
    int wid  = tid >> 5;
    int lane = tid & 31;
    int qid  = lane >> 2;
    int tq   = lane & 3;
    int mt   = wid >> 1;
    int ntb  = (wid & 1) * 4;

    if (tid < 64) ssv[tid] = 0.f;
    float sacc[4][4];
    #pragma unroll
    for (int i = 0; i < 4; i++)
        #pragma unroll
        for (int j = 0; j < 4; j++) sacc[i][j] = 0.f;
    float sv[4] = {0.f, 0.f, 0.f, 0.f};

    for (int ch = blockIdx.x; ch < nChunks; ch += gridDim.x) {
        const float4* ai4 = (const float4*)(g_att + (size_t)ch * 8192);
        __syncthreads();
        #pragma unroll
        for (int s = 0; s < 8; s++) {
            int v = tid + s * 256;           // channel base (v&15)*4 == (tid&15)*4
            float4 x = __ldcs(&ai4[v]);
            *(float4*)&sA[(v >> 4) * 68 + (v & 15) * 4] = x;
            sv[0] += x.x; sv[1] += x.y; sv[2] += x.z; sv[3] += x.w;
        }
        __syncthreads();
        #pragma unroll
        for (int ks = 0; ks < 16; ks++) {
            int kr = 8 * ks + tq;
            float a0 = sA[kr * 68 + 16 * mt + qid];
            float a1 = sA[kr * 68 + 16 * mt + qid + 8];
            float a2 = sA[(kr + 4) * 68 + 16 * mt + qid];
            float a3 = sA[(kr + 4) * 68 + 16 * mt + qid + 8];
            #pragma unroll
            for (int j = 0; j < 4; j++) {
                int nt = ntb + j;
                float b0 = sA[kr * 68 + 8 * nt + qid];
                float b1 = sA[(kr + 4) * 68 + 8 * nt + qid];
                mma8(sacc[j], a0, a1, a2, a3, b0, b1);
            }
        }
    }
    {
        int c4 = (tid & 15) * 4;
        atomicAdd(&ssv[c4],     sv[0]);
        atomicAdd(&ssv[c4 + 1], sv[1]);
        atomicAdd(&ssv[c4 + 2], sv[2]);
        atomicAdd(&ssv[c4 + 3], sv[3]);
    }
    #pragma unroll
    for (int j = 0; j < 4; j++) {
        int c1 = 16 * mt + qid;
        int c2 = 8 * (ntb + j) + 2 * tq;
        atomicAdd(&g_S[c1 * 64 + c2],           sacc[j][0]);
        atomicAdd(&g_S[c1 * 64 + c2 + 1],       sacc[j][1]);
        atomicAdd(&g_S[(c1 + 8) * 64 + c2],     sacc[j][2]);
        atomicAdd(&g_S[(c1 + 8) * 64 + c2 + 1], sacc[j][3]);
    }
    __syncthreads();
    if (tid < 64) atomicAdd(&g_svec[tid], ssv[tid]);
}

// ---------------------------------------------------------------------------
// K_bn1: moment trick, double-precision reduction.
// ---------------------------------------------------------------------------
__global__ void k_bn1(const float* __restrict__ bfc, const float* __restrict__ g1,
                      const float* __restrict__ b1, double invCnt) {
    __shared__ float sS[64 * 65];
    __shared__ float sw[64];
    __shared__ double red[4];
    int g = blockIdx.x;
    int i = threadIdx.x;
    sw[i] = g_Wfut[g * 64 + i];
    for (int l = i; l < 4096; l += 64)
        sS[(l >> 6) * 65 + (l & 63)] = g_S[l];
    __syncthreads();
    double y = 0.0;
    #pragma unroll 8
    for (int j = 0; j < 64; j++) y += (double)sS[i * 65 + j] * (double)sw[j];
    y *= (double)sw[i];
    double p = (double)sw[i] * (double)g_svec[i];
    #pragma unroll
    for (int off = 16; off > 0; off >>= 1) {
        y += __shfl_xor_sync(0xffffffffu, y, off);
        p += __shfl_xor_sync(0xffffffffu, p, off);
    }
    if ((i & 31) == 0) { red[(i >> 5) * 2] = y; red[(i >> 5) * 2 + 1] = p; }
    __syncthreads();
    if (i == 0) {
        double quad = red[0] + red[2];
        double lin  = red[1] + red[3];
        double b    = (double)bfc[g];
        double mean = lin * invCnt + b;
        double ex2  = (quad + 2.0 * b * lin) * invCnt + b * b;
        double var  = ex2 - mean * mean;
        double sc   = (double)g1[g] / sqrt(var + 1e-5);
        g_sc1[g] = (float)sc;
        g_sh1[g] = (float)((double)b1[g] - mean * sc);
    }
}

// ---------------------------------------------------------------------------
// K_gate: register-resident gated + tanh-sigmoid activation + reduction.
// ---------------------------------------------------------------------------
#define SMEM_GATE_FLOATS (48 * 68)
#define SMEM_GATE_BYTES (SMEM_GATE_FLOATS * 4)

__global__ __launch_bounds__(GBD, 3) void k_gate(const float* __restrict__ bfc, int N) {
    extern __shared__ float sm[];
    float* sA = sm;

    int tid  = threadIdx.x;
    int wid  = tid >> 5;
    int lane = tid & 31;
    int qid  = lane >> 2;
    int tq   = lane & 3;

    float bwf[8][2], bwh[8][2];
    float bbf[2], bbh[2];
    {
        int rf = wid * 8 + qid;
        int rh = 64 + wid * 8 + qid;
        float scf = g_sc1[rf], sch = g_sc1[rh];
        #pragma unroll
        for (int ks = 0; ks < 8; ks++) {
            bwf[ks][0] = tf32r(g_Wfut[rf * 64 + ks * 8 + tq] * scf);
            bwf[ks][1] = tf32r(g_Wfut[rf * 64 + ks * 8 + tq + 4] * scf);
            bwh[ks][0] = tf32r(g_Wfut[rh * 64 + ks * 8 + tq] * sch);
            bwh[ks][1] = tf32r(g_Wfut[rh * 64 + ks * 8 + tq + 4] * sch);
        }
        int cf = wid * 8 + 2 * tq;
        bbf[0] = bfc[cf]          * g_sc1[cf]          + g_sh1[cf];
        bbf[1] = bfc[cf + 1]      * g_sc1[cf + 1]      + g_sh1[cf + 1];
        bbh[0] = bfc[64 + cf]     * g_sc1[64 + cf]     + g_sh1[64 + cf];
        bbh[1] = bfc[64 + cf + 1] * g_sc1[64 + cf + 1] + g_sh1[64 + cf + 1];
    }
    float ls0 = 0.f, ls1 = 0.f, lq0 = 0.f, lq1 = 0.f;

    for (int grp = 0; grp < 8; grp++) {
        int n0 = blockIdx.x * APB + grp * 4;
        if (n0 >= N) break;

        const float4* ai4 = (const float4*)(g_att + (size_t)n0 * 768);
        #pragma unroll
        for (int s = 0; s < 3; s++) {
            int v = tid + s * GBD;           // 768 float4
            float4 x = __ldcs(&ai4[v]);
            *(float4*)&sA[(v >> 4) * 68 + (v & 15) * 4] = x;
        }
        __syncthreads();

        float acc[4][2];
        #pragma unroll
        for (int a = 0; a < 4; a++) { acc[a][0] = 0.f; acc[a][1] = 0.f; }

        #pragma unroll
        for (int mt = 0; mt < 3; mt++) {
            int r0 = 16 * mt + qid;
            float a[8][4];
            #pragma unroll
            for (int ks = 0; ks < 8; ks++) {
                int c0 = ks * 8 + tq;
                a[ks][0] = sA[r0 * 68 + c0];
                a[ks][1] = sA[(r0 + 8) * 68 + c0];
                a[ks][2] = sA[r0 * 68 + c0 + 4];
                a[ks][3] = sA[(r0 + 8) * 68 + c0 + 4];
            }
            float f[4] = {0.f, 0.f, 0.f, 0.f};
            float h[4] = {0.f, 0.f, 0.f, 0.f};
            #pragma unroll
            for (int ks = 0; ks < 8; ks++) {
                mma8(f, a[ks][0], a[ks][1], a[ks][2], a[ks][3], bwf[ks][0], bwf[ks][1]);
                mma8(h, a[ks][0], a[ks][1], a[ks][2], a[ks][3], bwh[ks][0], bwh[ks][1]);
            }
            float v0 = sigf(f[0] + bbf[0]) * spf2(h[0] + bbh[0]);
            float v1 = sigf(f[1] + bbf[1]) * spf2(h[1] + bbh[1]);
            float v2 = sigf(f[2] + bbf[0]) * spf2(h[2] + bbh[0]);
            float v3 = sigf(f[3] + bbf[1]) * spf2(h[3] + bbh[1]);
            if (mt == 0) {
                acc[0][0] += v0; acc[0][1] += v1;
                if (qid < 4) { acc[0][0] += v2; acc[0][1] += v3; }
                else         { acc[1][0] += v2; acc[1][1] += v3; }
            } else if (mt == 1) {
                acc[1][0] += v0; acc[1][1] += v1;
                acc[2][0] += v2; acc[2][1] += v3;
            } else {
                if (qid < 4) { acc[2][0] += v0; acc[2][1] += v1; }
                else         { acc[3][0] += v0; acc[3][1] += v1; }
                acc[3][0] += v2; acc[3][1] += v3;
            }
        }

        #pragma unroll
        for (int a = 0; a < 4; a++) {
            #pragma unroll
            for (int c = 0; c < 2; c++) {
                float v = acc[a][c];
                v += __shfl_xor_sync(0xffffffffu, v, 4);
                v += __shfl_xor_sync(0xffffffffu, v, 8);
                v += __shfl_xor_sync(0xffffffffu, v, 16);
                acc[a][c] = v;
            }
        }
        if (lane < 4) {
            int col = wid * 8 + 2 * lane;
            #pragma unroll
            for (int a = 0; a < 4; a++) {
                g_s[(size_t)(n0 + a) * 64 + col]     = acc[a][0];
                g_s[(size_t)(n0 + a) * 64 + col + 1] = acc[a][1];
                ls0 += acc[a][0]; lq0 += acc[a][0] * acc[a][0];
                ls1 += acc[a][1]; lq1 += acc[a][1] * acc[a][1];
            }
        }
        __syncthreads();
    }
    if (lane < 4) {
        int col = wid * 8 + 2 * lane;
        atomicAdd(&g_sum2[col],     ls0);
        atomicAdd(&g_sq2[col],      lq0);
        atomicAdd(&g_sum2[col + 1], ls1);
        atomicAdd(&g_sq2[col + 1],  lq1);
    }
}

// ---------------------------------------------------------------------------
// K_bn2: double-precision var computation.
// ---------------------------------------------------------------------------
__global__ void k_bn2(const float* __restrict__ g2, const float* __restrict__ b2, double invCnt) {
    int t = threadIdx.x;
    double m = (double)g_sum2[t] * invCnt;
    double v = (double)g_sq2[t] * invCnt - m * m;
    double sc = (double)g2[t] / sqrt(v + 1e-5);
    g_sc2[t] = (float)sc;
    g_sh2[t] = (float)((double)b2[t] - m * sc);
}

__global__ void k_final(const float* __restrict__ atom, float* __restrict__ out, int nVec) {
    int i = blockIdx.x * blockDim.x + threadIdx.x;
    if (i >= nVec) return;
    int c4 = (i & 15) * 4;
    float4 a = *(const float4*)&atom[(size_t)i * 4];
    float4 s = *(const float4*)&g_s[(size_t)i * 4];
    float4 o;
    o.x = spf2(a.x + s.x * g_sc2[c4]     + g_sh2[c4]);
    o.y = spf2(a.y + s.y * g_sc2[c4 + 1] + g_sh2[c4 + 1]);
    o.z = spf2(a.z + s.z * g_sc2[c4 + 2] + g_sh2[c4 + 2]);
    o.w = spf2(a.w + s.w * g_sc2[c4 + 3] + g_sh2[c4 + 3]);
    *(float4*)&out[(size_t)i * 4] = o;
}

// ---------------------------------------------------------------------------
extern "C" void kernel_launch(void* const* d_in, const int* in_sizes, int n_in,
                              void* d_out, int out_size) {
    const float* atom = (const float*)d_in[0];
    const float* nbr  = (const float*)d_in[1];
    const int*   idx  = (const int*)  d_in[2];
    const float* WK   = (const float*)d_in[3];
    const float* WQ   = (const float*)d_in[4];
    const float* WV   = (const float*)d_in[5];
    const float* WO   = (const float*)d_in[6];
    const float* Wfc  = (const float*)d_in[7];
    const float* bfc  = (const float*)d_in[8];
    const float* bn1g = (const float*)d_in[9];
    const float* bn1b = (const float*)d_in[10];
    const float* bn2g = (const float*)d_in[11];
    const float* bn2b = (const float*)d_in[12];
    float* out = (float*)d_out;

    int N = in_sizes[0] / ATOMF;
    int nChunks = (N * MNBR * ATOMF) / 8192;

    cudaFuncSetAttribute(k_main, cudaFuncAttributeMaxDynamicSharedMemorySize, SMEM_MAIN_BYTES);
    cudaFuncSetAttribute(k_gate, cudaFuncAttributeMaxDynamicSharedMemorySize, SMEM_GATE_BYTES);

    k_prep<<<192, 256>>>(WK, WQ, WV, Wfc, WO);
    k_projT<<<(N + 47) / 48, 384>>>(atom, N);
    k_main<<<(N + APB - 1) / APB, BD, SMEM_MAIN_BYTES>>>(nbr, idx, N);
    k_stats<<<1024, 256>>>(nChunks);     // 4th launch -> ncu profiles k_stats this round
    k_bn1<<<128, 64>>>(bfc, bn1g, bn1b, 1.0 / ((double)N * MNBR));
    k_gate<<<(N + APB - 1) / APB, GBD, SMEM_GATE_BYTES>>>(bfc, N);
    k_bn2<<<1, 64>>>(bn2g, bn2b, 1.0 / (double)N);
    k_final<<<(N * ATOMF / 4 + 255) / 256, 256>>>(atom, out, N * ATOMF / 4);
}

// round 15
// speedup vs baseline: 1.1600x; 1.0215x over previous
#include <cuda_runtime.h>
#include <cuda_fp16.h>

// ---------------------------------------------------------------------------
#define NMAX   65536
#define MNBR   12
#define ATOMF  64
#define INF_   192
#define BD     384
#define GBD    256
#define APB    32      // atoms per block (8 groups of 4)

// ---------------------------------------------------------------------------
__device__ float  g_Pself[NMAX * INF_];               // 48 MB
__device__ float  g_Pnbr [NMAX * INF_];               // 48 MB
__device__ __half g_att  [(size_t)NMAX * MNBR * 64];  // 100 MB (fp16 of tf32 — exact)
__device__ float  g_s    [NMAX * ATOMF];              // 16 MB
__device__ float  g_WEt  [192 * 64];                  // edge weights, tf32
__device__ float  g_Wall [384 * 64];                  // [self|nbr] proj weights, tf32
__device__ float  g_Wfut [128 * 64];                  // fused W_fc@WO, tf32
__device__ float  g_S    [64 * 64];
__device__ float  g_svec [64];
__device__ float  g_sum2[64], g_sq2[64];
__device__ float  g_sc1[128], g_sh1[128], g_sc2[64], g_sh2[64];

// ---------------------------------------------------------------------------
__device__ __forceinline__ float tf32r(float x) {
    unsigned u; asm("cvt.rna.tf32.f32 %0, %1;" : "=r"(u) : "f"(x));
    return __uint_as_float(u);
}
__device__ __forceinline__ void mma8(float d[4], float a0, float a1, float a2, float a3,
                                     float b0, float b1) {
    unsigned A0 = __float_as_uint(a0), A1 = __float_as_uint(a1);
    unsigned A2 = __float_as_uint(a2), A3 = __float_as_uint(a3);
    unsigned B0 = __float_as_uint(b0), B1 = __float_as_uint(b1);
    asm volatile("mma.sync.aligned.m16n8k8.row.col.f32.tf32.tf32.f32 "
                 "{%0,%1,%2,%3}, {%4,%5,%6,%7}, {%8,%9}, {%0,%1,%2,%3};"
                 : "+f"(d[0]), "+f"(d[1]), "+f"(d[2]), "+f"(d[3])
                 : "r"(A0), "r"(A1), "r"(A2), "r"(A3), "r"(B0), "r"(B1));
}
// sigmoid via single-MUFU tanh.approx
__device__ __forceinline__ float sigf(float x) {
    float t;
    asm("tanh.approx.f32 %0, %1;" : "=f"(t) : "f"(0.5f * x));
    return fmaf(0.5f, t, 0.5f);
}
__device__ __forceinline__ float spf2(float x) {
    return fmaxf(x, 0.f) + __logf(1.f + __expf(-fabsf(x)));
}
// pack two f32 -> f16x2 (x low, y high)
__device__ __forceinline__ unsigned packh2(float x, float y) {
    unsigned u;
    asm("cvt.rn.f16x2.f32 %0, %1, %2;" : "=r"(u) : "f"(y), "f"(x));
    return u;
}
// unpack uint (f16x2) -> float2
__device__ __forceinline__ float2 unph2(unsigned u) {
    __half2 h = *reinterpret_cast<__half2*>(&u);
    return __half22float2(h);
}

// ---------------------------------------------------------------------------
// K_prep: tf32-round WEt, Wall; fuse W_fc@WO; zero stats. grid 192 x 256.
// ---------------------------------------------------------------------------
__global__ void k_prep(const float* __restrict__ WK, const float* __restrict__ WQ,
                       const float* __restrict__ WV, const float* __restrict__ Wfc,
                       const float* __restrict__ WO) {
    int t = threadIdx.x;
    if (blockIdx.x == 0 && t < 64) {
        g_sum2[t] = 0.f; g_sq2[t] = 0.f; g_svec[t] = 0.f;
    }
    int o = blockIdx.x * 256 + t;
    if (o < 12288) {
        int j = o >> 6, f = o & 63;
        const float* W = (j < 64) ? WK : ((j < 128) ? WQ : WV);
        g_WEt[o] = tf32r(W[(j & 63) * INF_ + 128 + f]);
    } else if (o < 36864) {
        int p = o - 12288;
        int j = p >> 6, f = p & 63;
        int half = (j >= 192);
        int jj = half ? j - 192 : j;
        const float* W = (jj < 64) ? WK : ((jj < 128) ? WQ : WV);
        g_Wall[p] = tf32r(W[(jj & 63) * INF_ + (half ? 64 : 0) + f]);
    } else if (o < 45056) {
        int p = o - 36864;
        int g = p >> 6, a = p & 63;
        const float* wr = Wfc + g * 256;
        float acc = 0.f;
        #pragma unroll 8
        for (int q = 0; q < 256; q++) acc += wr[q] * WO[q * 64 + a];
        g_Wfut[p] = tf32r(acc);
    } else if (o < 49152) {
        g_S[o - 45056] = 0.f;
    }
}

// ---------------------------------------------------------------------------
// K_projT: tensorized per-atom projections (single-term tf32).
// ---------------------------------------------------------------------------
__global__ __launch_bounds__(384, 2) void k_projT(const float* __restrict__ atom, int N) {
    __shared__ float sAT[48 * 68];
    int tid = threadIdx.x, wid = tid >> 5, lane = tid & 31;
    int qid = lane >> 2, tq = lane & 3;
    int n0 = blockIdx.x * 48;

    #pragma unroll
    for (int s = 0; s < 8; s++) {
        int i = tid + s * 384;
        int r = i >> 6, c = i & 63;
        int n = n0 + r;
        float v = (n < N) ? atom[(size_t)n * 64 + c] : 0.f;
        sAT[r * 68 + c] = tf32r(v);
    }
    __syncthreads();

    #pragma unroll
    for (int half = 0; half < 2; half++) {
        const float* Wsrc = g_Wall + (half * 192 + wid * 16) * 64;
        float aw[8][4];
        #pragma unroll
        for (int ks = 0; ks < 8; ks++) {
            int f0 = ks * 8 + tq;
            aw[ks][0] = Wsrc[qid * 64 + f0];
            aw[ks][1] = Wsrc[(qid + 8) * 64 + f0];
            aw[ks][2] = Wsrc[qid * 64 + f0 + 4];
            aw[ks][3] = Wsrc[(qid + 8) * 64 + f0 + 4];
        }
        float* ob = half ? g_Pnbr : g_Pself;
        #pragma unroll
        for (int nt = 0; nt < 6; nt++) {
            float d[4] = {0.f, 0.f, 0.f, 0.f};
            const float* ar = sAT + (8 * nt + qid) * 68;
            #pragma unroll
            for (int ks = 0; ks < 8; ks++)
                mma8(d, aw[ks][0], aw[ks][1], aw[ks][2], aw[ks][3],
                     ar[ks * 8 + tq], ar[ks * 8 + tq + 4]);
            int r0  = 8 * nt + 2 * tq;
            int ch0 = wid * 16 + qid;
            if (n0 + r0 < N) {
                ob[(size_t)(n0 + r0) * INF_ + ch0]     = d[0];
                ob[(size_t)(n0 + r0) * INF_ + ch0 + 8] = d[2];
            }
            if (n0 + r0 + 1 < N) {
                ob[(size_t)(n0 + r0 + 1) * INF_ + ch0]     = d[1];
                ob[(size_t)(n0 + r0 + 1) * INF_ + ch0 + 8] = d[3];
            }
        }
    }
}

// ---------------------------------------------------------------------------
// K_main: champion pipeline; P5 stores fp16 att.
// ---------------------------------------------------------------------------
#define O_NF    0                 // 2 x 48x68 = 6528
#define O_KQV   6528              // 52 x 204 = 10608
#define O_LG    17136             // 4 x 272  = 1088
#define O_J     18224             // 2 x 48 ints
#define SMEM_FLOATS 18320
#define SMEM_MAIN_BYTES (SMEM_FLOATS * 4)

__global__ __launch_bounds__(BD, 2) void k_main(const float* __restrict__ nbr,
                                                const int*   __restrict__ idx,
                                                int N) {
    extern __shared__ float sm[];
    float* sNF0 = sm + O_NF;
    float* sNF1 = sm + O_NF + 3264;
    float* sKQV = sm + O_KQV;
    float* sLG  = sm + O_LG;
    int*   sJ0  = (int*)(sm + O_J);
    int*   sJ1  = sJ0 + 48;

    int tid  = threadIdx.x;
    int wid  = tid >> 5;
    int lane = tid & 31;
    int qid  = lane >> 2;
    int tq   = lane & 3;

    float aw[8][4];
    {
        int ch0 = 16 * wid + qid;
        #pragma unroll
        for (int ks = 0; ks < 8; ks++) {
            int f0 = ks * 8 + tq;
            aw[ks][0] = g_WEt[ch0 * 64 + f0];
            aw[ks][1] = g_WEt[(ch0 + 8) * 64 + f0];
            aw[ks][2] = g_WEt[ch0 * 64 + f0 + 4];
            aw[ks][3] = g_WEt[(ch0 + 8) * 64 + f0 + 4];
        }
    }

    // zero pad rows 48-51 of sKQV
    for (int i = tid; i < 4 * 204; i += BD) sKQV[48 * 204 + i] = 0.f;

    // prologue: NF(0) + sJ(0)
    {
        int n00 = blockIdx.x * APB;
        const float4* nb4 = (const float4*)(nbr + (size_t)n00 * 768);
        #pragma unroll
        for (int s = 0; s < 2; s++) {
            int v = tid + s * 384;          // 768 float4
            float4 x = __ldcs(&nb4[v]);
            x.x = tf32r(x.x); x.y = tf32r(x.y); x.z = tf32r(x.z); x.w = tf32r(x.w);
            *(float4*)&sNF0[(v >> 4) * 68 + (v & 15) * 4] = x;
        }
        if (tid < 48) sJ0[tid] = idx[n00 * MNBR + tid];
    }
    __syncthreads();

    for (int grp = 0; grp < 8; grp++) {
        int n0 = blockIdx.x * APB + grp * 4;
        if (n0 >= N) break;
        float* sNF  = (grp & 1) ? sNF1 : sNF0;
        int*   sJc  = (grp & 1) ? sJ1  : sJ0;
        float* sNFn = (grp & 1) ? sNF0 : sNF1;
        int*   sJn  = (grp & 1) ? sJ0  : sJ1;

        // ---- P1: vector gather -> sKQV (f32) ----
        #pragma unroll
        for (int s = 0; s < 6; s++) {
            int v  = tid + s * 384;          // 2304 float4 = 48 edges x 48
            int e  = v / 48;
            int c4 = (v - e * 48) * 4;
            int j  = sJc[e];
            int at = e / 12;
            float4 pn = *(const float4*)&g_Pnbr [(size_t)j * INF_ + c4];
            float4 ps = *(const float4*)&g_Pself[(size_t)(n0 + at) * INF_ + c4];
            float4 r;
            r.x = pn.x + ps.x; r.y = pn.y + ps.y;
            r.z = pn.z + ps.z; r.w = pn.w + ps.w;
            *(float4*)&sKQV[e * 204 + c4] = r;
        }
        __syncthreads();

        // ---- P2: edge MMA accumulating gather; epilogue tf32 ----
        {
            int ch0 = 16 * wid + qid;
            #pragma unroll
            for (int nt = 0; nt < 6; nt++) {
                int e0 = 8 * nt + 2 * tq;
                float d[4];
                d[0] = sKQV[e0 * 204 + ch0];
                d[1] = sKQV[(e0 + 1) * 204 + ch0];
                d[2] = sKQV[e0 * 204 + ch0 + 8];
                d[3] = sKQV[(e0 + 1) * 204 + ch0 + 8];
                const float* nrow = sNF + (8 * nt + qid) * 68;
                #pragma unroll
                for (int ks = 0; ks < 8; ks++) {
                    float b0 = nrow[ks * 8 + tq];
                    float b1 = nrow[ks * 8 + tq + 4];
                    mma8(d, aw[ks][0], aw[ks][1], aw[ks][2], aw[ks][3], b0, b1);
                }
                sKQV[e0 * 204 + ch0]           = tf32r(d[0]);
                sKQV[(e0 + 1) * 204 + ch0]     = tf32r(d[1]);
                sKQV[e0 * 204 + ch0 + 8]       = tf32r(d[2]);
                sKQV[(e0 + 1) * 204 + ch0 + 8] = tf32r(d[3]);
            }
        }
        __syncthreads();

        // ---- P3: logits+softmax (warps 0-3) | NF/idx prefetch (warps 4-11) ----
        if (wid < 4) {
            int a  = wid;
            int r0 = 12 * a;
            float d0[4] = {0.f, 0.f, 0.f, 0.f};
            float d1[4] = {0.f, 0.f, 0.f, 0.f};
            #pragma unroll
            for (int s = 0; s < 8; s++) {
                int f = 8 * s + tq;
                float a0 = sKQV[(r0 + qid) * 204 + f];
                float a1 = sKQV[(r0 + qid + 8) * 204 + f];
                float a2 = sKQV[(r0 + qid) * 204 + f + 4];
                float a3 = sKQV[(r0 + qid + 8) * 204 + f + 4];
                float b00 = sKQV[(r0 + qid) * 204 + 64 + f];
                float b01 = sKQV[(r0 + qid) * 204 + 64 + f + 4];
                float b10 = sKQV[(r0 + 8 + qid) * 204 + 64 + f];
                float b11 = sKQV[(r0 + 8 + qid) * 204 + 64 + f + 4];
                mma8(d0, a0, a1, a2, a3, b00, b01);
                mma8(d1, a0, a1, a2, a3, b10, b11);
            }
            float* lg = sLG + a * 272;
            bool colBad = (tq >= 2);
            {
                float l[4];
                l[0] = d0[0] * 0.125f; l[1] = d0[1] * 0.125f;
                l[2] = colBad ? -1e30f : d1[0] * 0.125f;
                l[3] = colBad ? -1e30f : d1[1] * 0.125f;
                float mx = fmaxf(fmaxf(l[0], l[1]), fmaxf(l[2], l[3]));
                mx = fmaxf(mx, __shfl_xor_sync(0xffffffffu, mx, 1));
                mx = fmaxf(mx, __shfl_xor_sync(0xffffffffu, mx, 2));
                float e0 = __expf(l[0] - mx), e1 = __expf(l[1] - mx);
                float e2 = __expf(l[2] - mx), e3 = __expf(l[3] - mx);
                float s = e0 + e1 + e2 + e3;
                s += __shfl_xor_sync(0xffffffffu, s, 1);
                s += __shfl_xor_sync(0xffffffffu, s, 2);
                float inv = 1.f / s;
                lg[qid * 17 + 2 * tq]         = tf32r(e0 * inv);
                lg[qid * 17 + 2 * tq + 1]     = tf32r(e1 * inv);
                lg[qid * 17 + 8 + 2 * tq]     = tf32r(e2 * inv);
                lg[qid * 17 + 8 + 2 * tq + 1] = tf32r(e3 * inv);
            }
            {
                bool rowOk = (qid < 4);
                float l[4];
                l[0] = d0[2] * 0.125f; l[1] = d0[3] * 0.125f;
                l[2] = colBad ? -1e30f : d1[2] * 0.125f;
                l[3] = colBad ? -1e30f : d1[3] * 0.125f;
                float mx = fmaxf(fmaxf(l[0], l[1]), fmaxf(l[2], l[3]));
                mx = fmaxf(mx, __shfl_xor_sync(0xffffffffu, mx, 1));
                mx = fmaxf(mx, __shfl_xor_sync(0xffffffffu, mx, 2));
                float e0 = __expf(l[0] - mx), e1 = __expf(l[1] - mx);
                float e2 = __expf(l[2] - mx), e3 = __expf(l[3] - mx);
                float s = e0 + e1 + e2 + e3;
                s += __shfl_xor_sync(0xffffffffu, s, 1);
                s += __shfl_xor_sync(0xffffffffu, s, 2);
                float inv = rowOk ? (1.f / s) : 0.f;
                lg[(qid + 8) * 17 + 2 * tq]         = tf32r(e0 * inv);
                lg[(qid + 8) * 17 + 2 * tq + 1]     = tf32r(e1 * inv);
                lg[(qid + 8) * 17 + 8 + 2 * tq]     = tf32r(e2 * inv);
                lg[(qid + 8) * 17 + 8 + 2 * tq + 1] = tf32r(e3 * inv);
            }
        } else if (grp < 7) {
            int n1 = n0 + 4;
            if (n1 < N) {
                int t2 = tid - 128;            // 0..255
                const float4* nb4 = (const float4*)(nbr + (size_t)n1 * 768);
                #pragma unroll
                for (int s = 0; s < 3; s++) {
                    int v = t2 + s * 256;      // 768 float4
                    float4 x = __ldcs(&nb4[v]);
                    x.x = tf32r(x.x); x.y = tf32r(x.y); x.z = tf32r(x.z); x.w = tf32r(x.w);
                    *(float4*)&sNFn[(v >> 4) * 68 + (v & 15) * 4] = x;
                }
                if (t2 < 48) sJn[t2] = idx[n1 * MNBR + t2];
            }
        }
        __syncthreads();

        // ---- P5: attn = W @ V MMA -> fp16 STG to g_att ----
        if (wid < 8) {
            int a = wid >> 1;
            int ntb = (wid & 1) * 4;
            const float* lg = sLG + a * 272;
            float af[2][4];
            #pragma unroll
            for (int s = 0; s < 2; s++) {
                int k = 8 * s + tq;
                af[s][0] = lg[qid * 17 + k];
                af[s][1] = lg[(qid + 8) * 17 + k];
                af[s][2] = lg[qid * 17 + k + 4];
                af[s][3] = lg[(qid + 8) * 17 + k + 4];
            }
            __half* go = g_att + (size_t)n0 * 768 + 12 * a * 64;
            #pragma unroll
            for (int j = 0; j < 4; j++) {
                int nt = ntb + j;
                float d[4] = {0.f, 0.f, 0.f, 0.f};
                #pragma unroll
                for (int s = 0; s < 2; s++) {
                    int kr = 12 * a + 8 * s + tq;
                    float b0 = sKQV[kr * 204 + 128 + 8 * nt + qid];
                    float b1 = sKQV[(kr + 4) * 204 + 128 + 8 * nt + qid];
                    mma8(d, af[s][0], af[s][1], af[s][2], af[s][3], b0, b1);
                }
                int col = 8 * nt + 2 * tq;
                unsigned u0 = packh2(d[0], d[1]);
                __stcs((unsigned int*)&go[qid * 64 + col], u0);
                if (qid < 4) {
                    unsigned u1 = packh2(d[2], d[3]);
                    __stcs((unsigned int*)&go[(qid + 8) * 64 + col], u1);
                }
            }
        }
        __syncthreads();   // sKQV reused next group
    }
}

// ---------------------------------------------------------------------------
// K_stats: S = att^T @ att + svec (per-channel), fp16 streaming loads.
// ---------------------------------------------------------------------------
__global__ __launch_bounds__(256, 4) void k_stats(int nChunks) {
    __shared__ float sA[128 * 68];
    __shared__ float ssv[64];
    int tid  = threadIdx.x;
    int wid  = tid >> 5;
    int lane = tid & 31;
    int qid  = lane >> 2;
    int tq   = lane & 3;
    int mt   = wid >> 1;
    int ntb  = (wid & 1) * 4;

    if (tid < 64) ssv[tid] = 0.f;
    float sacc[4][4];
    #pragma unroll
    for (int i = 0; i < 4; i++)
        #pragma unroll
        for (int j = 0; j < 4; j++) sacc[i][j] = 0.f;
    float sv[4] = {0.f, 0.f, 0.f, 0.f};

    for (int ch = blockIdx.x; ch < nChunks; ch += gridDim.x) {
        const uint2* ai2 = (const uint2*)(g_att + (size_t)ch * 8192);
        __syncthreads();
        #pragma unroll
        for (int s = 0; s < 8; s++) {
            int v = tid + s * 256;           // 2048 uint2; row v>>4, chan base (v&15)*4
            uint2 u = __ldcs(&ai2[v]);
            float2 f0 = unph2(u.x);
            float2 f1 = unph2(u.y);
            float4 x = {f0.x, f0.y, f1.x, f1.y};
            *(float4*)&sA[(v >> 4) * 68 + (v & 15) * 4] = x;
            sv[0] += x.x; sv[1] += x.y; sv[2] += x.z; sv[3] += x.w;
        }
        __syncthreads();
        #pragma unroll
        for (int ks = 0; ks < 16; ks++) {
            int kr = 8 * ks + tq;
            float a0 = sA[kr * 68 + 16 * mt + qid];
            float a1 = sA[kr * 68 + 16 * mt + qid + 8];
            float a2 = sA[(kr + 4) * 68 + 16 * mt + qid];
            float a3 = sA[(kr + 4) * 68 + 16 * mt + qid + 8];
            #pragma unroll
            for (int j = 0; j < 4; j++) {
                int nt = ntb + j;
                float b0 = sA[kr * 68 + 8 * nt + qid];
                float b1 = sA[(kr + 4) * 68 + 8 * nt + qid];
                mma8(sacc[j], a0, a1, a2, a3, b0, b1);
            }
        }
    }
    {
        int c4 = (tid & 15) * 4;
        atomicAdd(&ssv[c4],     sv[0]);
        atomicAdd(&ssv[c4 + 1], sv[1]);
        atomicAdd(&ssv[c4 + 2], sv[2]);
        atomicAdd(&ssv[c4 + 3], sv[3]);
    }
    #pragma unroll
    for (int j = 0; j < 4; j++) {
        int c1 = 16 * mt + qid;
        int c2 = 8 * (ntb + j) + 2 * tq;
        atomicAdd(&g_S[c1 * 64 + c2],           sacc[j][0]);
        atomicAdd(&g_S[c1 * 64 + c2 + 1],       sacc[j][1]);
        atomicAdd(&g_S[(c1 + 8) * 64 + c2],     sacc[j][2]);
        atomicAdd(&g_S[(c1 + 8) * 64 + c2 + 1], sacc[j][3]);
    }
    __syncthreads();
    if (tid < 64) atomicAdd(&g_svec[tid], ssv[tid]);
}

// ---------------------------------------------------------------------------
// K_bn1: moment trick, double-precision reduction.
// ---------------------------------------------------------------------------
__global__ void k_bn1(const float* __restrict__ bfc, const float* __restrict__ g1,
                      const float* __restrict__ b1, double invCnt) {
    __shared__ float sS[64 * 65];
    __shared__ float sw[64];
    __shared__ double red[4];
    int g = blockIdx.x;
    int i = threadIdx.x;
    sw[i] = g_Wfut[g * 64 + i];
    for (int l = i; l < 4096; l += 64)
        sS[(l >> 6) * 65 + (l & 63)] = g_S[l];
    __syncthreads();
    double y = 0.0;
    #pragma unroll 8
    for (int j = 0; j < 64; j++) y += (double)sS[i * 65 + j] * (double)sw[j];
    y *= (double)sw[i];
    double p = (double)sw[i] * (double)g_svec[i];
    #pragma unroll
    for (int off = 16; off > 0; off >>= 1) {
        y += __shfl_xor_sync(0xffffffffu, y, off);
        p += __shfl_xor_sync(0xffffffffu, p, off);
    }
    if ((i & 31) == 0) { red[(i >> 5) * 2] = y; red[(i >> 5) * 2 + 1] = p; }
    __syncthreads();
    if (i == 0) {
        double quad = red[0] + red[2];
        double lin  = red[1] + red[3];
        double b    = (double)bfc[g];
        double mean = lin * invCnt + b;
        double ex2  = (quad + 2.0 * b * lin) * invCnt + b * b;
        double var  = ex2 - mean * mean;
        double sc   = (double)g1[g] / sqrt(var + 1e-5);
        g_sc1[g] = (float)sc;
        g_sh1[g] = (float)((double)b1[g] - mean * sc);
    }
}

// ---------------------------------------------------------------------------
// K_gate: register-resident gated + tanh-sigmoid activation + reduction.
// fp16 att loads.
// ---------------------------------------------------------------------------
#define SMEM_GATE_FLOATS (48 * 68)
#define SMEM_GATE_BYTES (SMEM_GATE_FLOATS * 4)

__global__ __launch_bounds__(GBD, 3) void k_gate(const float* __restrict__ bfc, int N) {
    extern __shared__ float sm[];
    float* sA = sm;

    int tid  = threadIdx.x;
    int wid  = tid >> 5;
    int lane = tid & 31;
    int qid  = lane >> 2;
    int tq   = lane & 3;

    float bwf[8][2], bwh[8][2];
    float bbf[2], bbh[2];
    {
        int rf = wid * 8 + qid;
        int rh = 64 + wid * 8 + qid;
        float scf = g_sc1[rf], sch = g_sc1[rh];
        #pragma unroll
        for (int ks = 0; ks < 8; ks++) {
            bwf[ks][0] = tf32r(g_Wfut[rf * 64 + ks * 8 + tq] * scf);
            bwf[ks][1] = tf32r(g_Wfut[rf * 64 + ks * 8 + tq + 4] * scf);
            bwh[ks][0] = tf32r(g_Wfut[rh * 64 + ks * 8 + tq] * sch);
            bwh[ks][1] = tf32r(g_Wfut[rh * 64 + ks * 8 + tq + 4] * sch);
        }
        int cf = wid * 8 + 2 * tq;
        bbf[0] = bfc[cf]          * g_sc1[cf]          + g_sh1[cf];
        bbf[1] = bfc[cf + 1]      * g_sc1[cf + 1]      + g_sh1[cf + 1];
        bbh[0] = bfc[64 + cf]     * g_sc1[64 + cf]     + g_sh1[64 + cf];
        bbh[1] = bfc[64 + cf + 1] * g_sc1[64 + cf + 1] + g_sh1[64 + cf + 1];
    }
    float ls0 = 0.f, ls1 = 0.f, lq0 = 0.f, lq1 = 0.f;

    for (int grp = 0; grp < 8; grp++) {
        int n0 = blockIdx.x * APB + grp * 4;
        if (n0 >= N) break;

        const uint2* ai2 = (const uint2*)(g_att + (size_t)n0 * 768);
        #pragma unroll
        for (int s = 0; s < 3; s++) {
            int v = tid + s * GBD;           // 768 uint2; row v>>4, chan base (v&15)*4
            uint2 u = __ldcs(&ai2[v]);
            float2 f0 = unph2(u.x);
            float2 f1 = unph2(u.y);
            float4 x = {f0.x, f0.y, f1.x, f1.y};
            *(float4*)&sA[(v >> 4) * 68 + (v & 15) * 4] = x;
        }
        __syncthreads();

        float acc[4][2];
        #pragma unroll
        for (int a = 0; a < 4; a++) { acc[a][0] = 0.f; acc[a][1] = 0.f; }

        #pragma unroll
        for (int mt = 0; mt < 3; mt++) {
            int r0 = 16 * mt + qid;
            float a[8][4];
            #pragma unroll
            for (int ks = 0; ks < 8; ks++) {
                int c0 = ks * 8 + tq;
                a[ks][0] = sA[r0 * 68 + c0];
                a[ks][1] = sA[(r0 + 8) * 68 + c0];
                a[ks][2] = sA[r0 * 68 + c0 + 4];
                a[ks][3] = sA[(r0 + 8) * 68 + c0 + 4];
            }
            float f[4] = {0.f, 0.f, 0.f, 0.f};
            float h[4] = {0.f, 0.f, 0.f, 0.f};
            #pragma unroll
            for (int ks = 0; ks < 8; ks++) {
                mma8(f, a[ks][0], a[ks][1], a[ks][2], a[ks][3], bwf[ks][0], bwf[ks][1]);
                mma8(h, a[ks][0], a[ks][1], a[ks][2], a[ks][3], bwh[ks][0], bwh[ks][1]);
            }
            float v0 = sigf(f[0] + bbf[0]) * spf2(h[0] + bbh[0]);
            float v1 = sigf(f[1] + bbf[1]) * spf2(h[1] + bbh[1]);
            float v2 = sigf(f[2] + bbf[0]) * spf2(h[2] + bbh[0]);
            float v3 = sigf(f[3] + bbf[1]) * spf2(h[3] + bbh[1]);
            if (mt == 0) {
                acc[0][0] += v0; acc[0][1] += v1;
                if (qid < 4) { acc[0][0] += v2; acc[0][1] += v3; }
                else         { acc[1][0] += v2; acc[1][1] += v3; }
            } else if (mt == 1) {
                acc[1][0] += v0; acc[1][1] += v1;
                acc[2][0] += v2; acc[2][1] += v3;
            } else {
                if (qid < 4) { acc[2][0] += v0; acc[2][1] += v1; }
                else         { acc[3][0] += v0; acc[3][1] += v1; }
                acc[3][0] += v2; acc[3][1] += v3;
            }
        }

        #pragma unroll
        for (int a = 0; a < 4; a++) {
            #pragma unroll
            for (int c = 0; c < 2; c++) {
                float v = acc[a][c];
                v += __shfl_xor_sync(0xffffffffu, v, 4);
                v += __shfl_xor_sync(0xffffffffu, v, 8);
                v += __shfl_xor_sync(0xffffffffu, v, 16);
                acc[a][c] = v;
            }
        }
        if (lane < 4) {
            int col = wid * 8 + 2 * lane;
            #pragma unroll
            for (int a = 0; a < 4; a++) {
                g_s[(size_t)(n0 + a) * 64 + col]     = acc[a][0];
                g_s[(size_t)(n0 + a) * 64 + col + 1] = acc[a][1];
                ls0 += acc[a][0]; lq0 += acc[a][0] * acc[a][0];
                ls1 += acc[a][1]; lq1 += acc[a][1] * acc[a][1];
            }
        }
        __syncthreads();
    }
    if (lane < 4) {
        int col = wid * 8 + 2 * lane;
        atomicAdd(&g_sum2[col],     ls0);
        atomicAdd(&g_sq2[col],      lq0);
        atomicAdd(&g_sum2[col + 1], ls1);
        atomicAdd(&g_sq2[col + 1],  lq1);
    }
}

// ---------------------------------------------------------------------------
// K_bn2: double-precision var computation.
// ---------------------------------------------------------------------------
__global__ void k_bn2(const float* __restrict__ g2, const float* __restrict__ b2, double invCnt) {
    int t = threadIdx.x;
    double m = (double)g_sum2[t] * invCnt;
    double v = (double)g_sq2[t] * invCnt - m * m;
    double sc = (double)g2[t] / sqrt(v + 1e-5);
    g_sc2[t] = (float)sc;
    g_sh2[t] = (float)((double)b2[t] - m * sc);
}

__global__ void k_final(const float* __restrict__ atom, float* __restrict__ out, int nVec) {
    int i = blockIdx.x * blockDim.x + threadIdx.x;
    if (i >= nVec) return;
    int c4 = (i & 15) * 4;
    float4 a = *(const float4*)&atom[(size_t)i * 4];
    float4 s = *(const float4*)&g_s[(size_t)i * 4];
    float4 o;
    o.x = spf2(a.x + s.x * g_sc2[c4]     + g_sh2[c4]);
    o.y = spf2(a.y + s.y * g_sc2[c4 + 1] + g_sh2[c4 + 1]);
    o.z = spf2(a.z + s.z * g_sc2[c4 + 2] + g_sh2[c4 + 2]);
    o.w = spf2(a.w + s.w * g_sc2[c4 + 3] + g_sh2[c4 + 3]);
    *(float4*)&out[(size_t)i * 4] = o;
}

// ---------------------------------------------------------------------------
extern "C" void kernel_launch(void* const* d_in, const int* in_sizes, int n_in,
                              void* d_out, int out_size) {
    const float* atom = (const float*)d_in[0];
    const float* nbr  = (const float*)d_in[1];
    const int*   idx  = (const int*)  d_in[2];
    const float* WK   = (const float*)d_in[3];
    const float* WQ   = (const float*)d_in[4];
    const float* WV   = (const float*)d_in[5];
    const float* WO   = (const float*)d_in[6];
    const float* Wfc  = (const float*)d_in[7];
    const float* bfc  = (const float*)d_in[8];
    const float* bn1g = (const float*)d_in[9];
    const float* bn1b = (const float*)d_in[10];
    const float* bn2g = (const float*)d_in[11];
    const float* bn2b = (const float*)d_in[12];
    float* out = (float*)d_out;

    int N = in_sizes[0] / ATOMF;
    int nChunks = (N * MNBR * ATOMF) / 8192;

    cudaFuncSetAttribute(k_main, cudaFuncAttributeMaxDynamicSharedMemorySize, SMEM_MAIN_BYTES);
    cudaFuncSetAttribute(k_gate, cudaFuncAttributeMaxDynamicSharedMemorySize, SMEM_GATE_BYTES);

    k_prep<<<192, 256>>>(WK, WQ, WV, Wfc, WO);
    k_projT<<<(N + 47) / 48, 384>>>(atom, N);
    k_main<<<(N + APB - 1) / APB, BD, SMEM_MAIN_BYTES>>>(nbr, idx, N);
    k_stats<<<1024, 256>>>(nChunks);
    k_bn1<<<128, 64>>>(bfc, bn1g, bn1b, 1.0 / ((double)N * MNBR));
    k_gate<<<(N + APB - 1) / APB, GBD, SMEM_GATE_BYTES>>>(bfc, N);
    k_bn2<<<1, 64>>>(bn2g, bn2b, 1.0 / (double)N);
    k_final<<<(N * ATOMF / 4 + 255) / 256, 256>>>(atom, out, N * ATOMF / 4);
}

// round 16
// speedup vs baseline: 1.2465x; 1.0745x over previous
#include <cuda_runtime.h>
#include <cuda_fp16.h>

// ---------------------------------------------------------------------------
#define NMAX   65536
#define MNBR   12
#define ATOMF  64
#define INF_   192
#define BD     384
#define GBD    256
#define APB    32      // atoms per block (8 groups of 4)

// ---------------------------------------------------------------------------
__device__ __half g_Pself[NMAX * INF_];               // 24 MB (fp16)
__device__ __half g_Pnbr [NMAX * INF_];               // 24 MB (fp16)
__device__ __half g_att  [(size_t)NMAX * MNBR * 64];  // 100 MB (fp16 of tf32)
__device__ float  g_s    [NMAX * ATOMF];              // 16 MB
__device__ float  g_WEt  [192 * 64];                  // edge weights, tf32
__device__ float  g_Wall [384 * 64];                  // [self|nbr] proj weights, tf32
__device__ float  g_Wfut [128 * 64];                  // fused W_fc@WO, tf32
__device__ float  g_S    [64 * 64];
__device__ float  g_svec [64];
__device__ float  g_sum2[64], g_sq2[64];
__device__ float  g_sc1[128], g_sh1[128], g_sc2[64], g_sh2[64];

// ---------------------------------------------------------------------------
__device__ __forceinline__ float tf32r(float x) {
    unsigned u; asm("cvt.rna.tf32.f32 %0, %1;" : "=r"(u) : "f"(x));
    return __uint_as_float(u);
}
__device__ __forceinline__ void mma8(float d[4], float a0, float a1, float a2, float a3,
                                     float b0, float b1) {
    unsigned A0 = __float_as_uint(a0), A1 = __float_as_uint(a1);
    unsigned A2 = __float_as_uint(a2), A3 = __float_as_uint(a3);
    unsigned B0 = __float_as_uint(b0), B1 = __float_as_uint(b1);
    asm volatile("mma.sync.aligned.m16n8k8.row.col.f32.tf32.tf32.f32 "
                 "{%0,%1,%2,%3}, {%4,%5,%6,%7}, {%8,%9}, {%0,%1,%2,%3};"
                 : "+f"(d[0]), "+f"(d[1]), "+f"(d[2]), "+f"(d[3])
                 : "r"(A0), "r"(A1), "r"(A2), "r"(A3), "r"(B0), "r"(B1));
}
// sigmoid via single-MUFU tanh.approx
__device__ __forceinline__ float sigf(float x) {
    float t;
    asm("tanh.approx.f32 %0, %1;" : "=f"(t) : "f"(0.5f * x));
    return fmaf(0.5f, t, 0.5f);
}
__device__ __forceinline__ float spf2(float x) {
    return fmaxf(x, 0.f) + __logf(1.f + __expf(-fabsf(x)));
}
__device__ __forceinline__ unsigned packh2(float x, float y) {
    unsigned u;
    asm("cvt.rn.f16x2.f32 %0, %1, %2;" : "=r"(u) : "f"(y), "f"(x));
    return u;
}
__device__ __forceinline__ float2 unph2(unsigned u) {
    __half2 h = *reinterpret_cast<__half2*>(&u);
    return __half22float2(h);
}

// ---------------------------------------------------------------------------
// K_prep: tf32-round WEt, Wall; fuse W_fc@WO; zero stats. grid 192 x 256.
// ---------------------------------------------------------------------------
__global__ void k_prep(const float* __restrict__ WK, const float* __restrict__ WQ,
                       const float* __restrict__ WV, const float* __restrict__ Wfc,
                       const float* __restrict__ WO) {
    int t = threadIdx.x;
    if (blockIdx.x == 0 && t < 64) {
        g_sum2[t] = 0.f; g_sq2[t] = 0.f; g_svec[t] = 0.f;
    }
    int o = blockIdx.x * 256 + t;
    if (o < 12288) {
        int j = o >> 6, f = o & 63;
        const float* W = (j < 64) ? WK : ((j < 128) ? WQ : WV);
        g_WEt[o] = tf32r(W[(j & 63) * INF_ + 128 + f]);
    } else if (o < 36864) {
        int p = o - 12288;
        int j = p >> 6, f = p & 63;
        int half = (j >= 192);
        int jj = half ? j - 192 : j;
        const float* W = (jj < 64) ? WK : ((jj < 128) ? WQ : WV);
        g_Wall[p] = tf32r(W[(jj & 63) * INF_ + (half ? 64 : 0) + f]);
    } else if (o < 45056) {
        int p = o - 36864;
        int g = p >> 6, a = p & 63;
        const float* wr = Wfc + g * 256;
        float acc = 0.f;
        #pragma unroll 8
        for (int q = 0; q < 256; q++) acc += wr[q] * WO[q * 64 + a];
        g_Wfut[p] = tf32r(acc);
    } else if (o < 49152) {
        g_S[o - 45056] = 0.f;
    }
}

// ---------------------------------------------------------------------------
// K_projT: tensorized per-atom projections -> fp16 P arrays.
// ---------------------------------------------------------------------------
__global__ __launch_bounds__(384, 2) void k_projT(const float* __restrict__ atom, int N) {
    __shared__ float sAT[48 * 68];
    int tid = threadIdx.x, wid = tid >> 5, lane = tid & 31;
    int qid = lane >> 2, tq = lane & 3;
    int n0 = blockIdx.x * 48;

    #pragma unroll
    for (int s = 0; s < 8; s++) {
        int i = tid + s * 384;
        int r = i >> 6, c = i & 63;
        int n = n0 + r;
        float v = (n < N) ? atom[(size_t)n * 64 + c] : 0.f;
        sAT[r * 68 + c] = tf32r(v);
    }
    __syncthreads();

    #pragma unroll
    for (int half = 0; half < 2; half++) {
        const float* Wsrc = g_Wall + (half * 192 + wid * 16) * 64;
        float aw[8][4];
        #pragma unroll
        for (int ks = 0; ks < 8; ks++) {
            int f0 = ks * 8 + tq;
            aw[ks][0] = Wsrc[qid * 64 + f0];
            aw[ks][1] = Wsrc[(qid + 8) * 64 + f0];
            aw[ks][2] = Wsrc[qid * 64 + f0 + 4];
            aw[ks][3] = Wsrc[(qid + 8) * 64 + f0 + 4];
        }
        __half* ob = half ? g_Pnbr : g_Pself;
        #pragma unroll
        for (int nt = 0; nt < 6; nt++) {
            float d[4] = {0.f, 0.f, 0.f, 0.f};
            const float* ar = sAT + (8 * nt + qid) * 68;
            #pragma unroll
            for (int ks = 0; ks < 8; ks++)
                mma8(d, aw[ks][0], aw[ks][1], aw[ks][2], aw[ks][3],
                     ar[ks * 8 + tq], ar[ks * 8 + tq + 4]);
            int r0  = 8 * nt + 2 * tq;
            int ch0 = wid * 16 + qid;
            if (n0 + r0 < N) {
                ob[(size_t)(n0 + r0) * INF_ + ch0]     = __float2half(d[0]);
                ob[(size_t)(n0 + r0) * INF_ + ch0 + 8] = __float2half(d[2]);
            }
            if (n0 + r0 + 1 < N) {
                ob[(size_t)(n0 + r0 + 1) * INF_ + ch0]     = __float2half(d[1]);
                ob[(size_t)(n0 + r0 + 1) * INF_ + ch0 + 8] = __float2half(d[3]);
            }
        }
    }
}

// ---------------------------------------------------------------------------
// K_main: champion pipeline; fp16 P gather, fp16 att store.
// ---------------------------------------------------------------------------
#define O_NF    0                 // 2 x 48x68 = 6528
#define O_KQV   6528              // 52 x 204 = 10608
#define O_LG    17136             // 4 x 272  = 1088
#define O_J     18224             // 2 x 48 ints
#define SMEM_FLOATS 18320
#define SMEM_MAIN_BYTES (SMEM_FLOATS * 4)

__global__ __launch_bounds__(BD, 2) void k_main(const float* __restrict__ nbr,
                                                const int*   __restrict__ idx,
                                                int N) {
    extern __shared__ float sm[];
    float* sNF0 = sm + O_NF;
    float* sNF1 = sm + O_NF + 3264;
    float* sKQV = sm + O_KQV;
    float* sLG  = sm + O_LG;
    int*   sJ0  = (int*)(sm + O_J);
    int*   sJ1  = sJ0 + 48;

    int tid  = threadIdx.x;
    int wid  = tid >> 5;
    int lane = tid & 31;
    int qid  = lane >> 2;
    int tq   = lane & 3;

    float aw[8][4];
    {
        int ch0 = 16 * wid + qid;
        #pragma unroll
        for (int ks = 0; ks < 8; ks++) {
            int f0 = ks * 8 + tq;
            aw[ks][0] = g_WEt[ch0 * 64 + f0];
            aw[ks][1] = g_WEt[(ch0 + 8) * 64 + f0];
            aw[ks][2] = g_WEt[ch0 * 64 + f0 + 4];
            aw[ks][3] = g_WEt[(ch0 + 8) * 64 + f0 + 4];
        }
    }

    // zero pad rows 48-51 of sKQV
    for (int i = tid; i < 4 * 204; i += BD) sKQV[48 * 204 + i] = 0.f;

    // prologue: NF(0) + sJ(0)
    {
        int n00 = blockIdx.x * APB;
        const float4* nb4 = (const float4*)(nbr + (size_t)n00 * 768);
        #pragma unroll
        for (int s = 0; s < 2; s++) {
            int v = tid + s * 384;          // 768 float4
            float4 x = __ldcs(&nb4[v]);
            x.x = tf32r(x.x); x.y = tf32r(x.y); x.z = tf32r(x.z); x.w = tf32r(x.w);
            *(float4*)&sNF0[(v >> 4) * 68 + (v & 15) * 4] = x;
        }
        if (tid < 48) sJ0[tid] = idx[n00 * MNBR + tid];
    }
    __syncthreads();

    for (int grp = 0; grp < 8; grp++) {
        int n0 = blockIdx.x * APB + grp * 4;
        if (n0 >= N) break;
        float* sNF  = (grp & 1) ? sNF1 : sNF0;
        int*   sJc  = (grp & 1) ? sJ1  : sJ0;
        float* sNFn = (grp & 1) ? sNF0 : sNF1;
        int*   sJn  = (grp & 1) ? sJ0  : sJ1;

        // ---- P1: fp16 vector gather -> sKQV (f32 adds) ----
        #pragma unroll
        for (int s = 0; s < 3; s++) {
            int v  = tid + s * 384;          // 1152 uint4 = 48 edges x 24
            int e  = v / 24;
            int c8 = (v - e * 24) * 8;
            int j  = sJc[e];
            int at = e / 12;
            uint4 pn = *(const uint4*)&g_Pnbr [(size_t)j * INF_ + c8];
            uint4 ps = *(const uint4*)&g_Pself[(size_t)(n0 + at) * INF_ + c8];
            float2 a0 = unph2(pn.x), b0 = unph2(ps.x);
            float2 a1 = unph2(pn.y), b1 = unph2(ps.y);
            float2 a2 = unph2(pn.z), b2 = unph2(ps.z);
            float2 a3 = unph2(pn.w), b3 = unph2(ps.w);
            float4 r0 = {a0.x + b0.x, a0.y + b0.y, a1.x + b1.x, a1.y + b1.y};
            float4 r1 = {a2.x + b2.x, a2.y + b2.y, a3.x + b3.x, a3.y + b3.y};
            *(float4*)&sKQV[e * 204 + c8]     = r0;
            *(float4*)&sKQV[e * 204 + c8 + 4] = r1;
        }
        __syncthreads();

        // ---- P2: edge MMA accumulating gather; epilogue tf32 ----
        {
            int ch0 = 16 * wid + qid;
            #pragma unroll
            for (int nt = 0; nt < 6; nt++) {
                int e0 = 8 * nt + 2 * tq;
                float d[4];
                d[0] = sKQV[e0 * 204 + ch0];
                d[1] = sKQV[(e0 + 1) * 204 + ch0];
                d[2] = sKQV[e0 * 204 + ch0 + 8];
                d[3] = sKQV[(e0 + 1) * 204 + ch0 + 8];
                const float* nrow = sNF + (8 * nt + qid) * 68;
                #pragma unroll
                for (int ks = 0; ks < 8; ks++) {
                    float b0 = nrow[ks * 8 + tq];
                    float b1 = nrow[ks * 8 + tq + 4];
                    mma8(d, aw[ks][0], aw[ks][1], aw[ks][2], aw[ks][3], b0, b1);
                }
                sKQV[e0 * 204 + ch0]           = tf32r(d[0]);
                sKQV[(e0 + 1) * 204 + ch0]     = tf32r(d[1]);
                sKQV[e0 * 204 + ch0 + 8]       = tf32r(d[2]);
                sKQV[(e0 + 1) * 204 + ch0 + 8] = tf32r(d[3]);
            }
        }
        __syncthreads();

        // ---- P3: logits+softmax (warps 0-3) | NF/idx prefetch (warps 4-11) ----
        if (wid < 4) {
            int a  = wid;
            int r0 = 12 * a;
            float d0[4] = {0.f, 0.f, 0.f, 0.f};
            float d1[4] = {0.f, 0.f, 0.f, 0.f};
            #pragma unroll
            for (int s = 0; s < 8; s++) {
                int f = 8 * s + tq;
                float a0 = sKQV[(r0 + qid) * 204 + f];
                float a1 = sKQV[(r0 + qid + 8) * 204 + f];
                float a2 = sKQV[(r0 + qid) * 204 + f + 4];
                float a3 = sKQV[(r0 + qid + 8) * 204 + f + 4];
                float b00 = sKQV[(r0 + qid) * 204 + 64 + f];
                float b01 = sKQV[(r0 + qid) * 204 + 64 + f + 4];
                float b10 = sKQV[(r0 + 8 + qid) * 204 + 64 + f];
                float b11 = sKQV[(r0 + 8 + qid) * 204 + 64 + f + 4];
                mma8(d0, a0, a1, a2, a3, b00, b01);
                mma8(d1, a0, a1, a2, a3, b10, b11);
            }
            float* lg = sLG + a * 272;
            bool colBad = (tq >= 2);
            {
                float l[4];
                l[0] = d0[0] * 0.125f; l[1] = d0[1] * 0.125f;
                l[2] = colBad ? -1e30f : d1[0] * 0.125f;
                l[3] = colBad ? -1e30f : d1[1] * 0.125f;
                float mx = fmaxf(fmaxf(l[0], l[1]), fmaxf(l[2], l[3]));
                mx = fmaxf(mx, __shfl_xor_sync(0xffffffffu, mx, 1));
                mx = fmaxf(mx, __shfl_xor_sync(0xffffffffu, mx, 2));
                float e0 = __expf(l[0] - mx), e1 = __expf(l[1] - mx);
                float e2 = __expf(l[2] - mx), e3 = __expf(l[3] - mx);
                float s = e0 + e1 + e2 + e3;
                s += __shfl_xor_sync(0xffffffffu, s, 1);
                s += __shfl_xor_sync(0xffffffffu, s, 2);
                float inv = 1.f / s;
                lg[qid * 17 + 2 * tq]         = tf32r(e0 * inv);
                lg[qid * 17 + 2 * tq + 1]     = tf32r(e1 * inv);
                lg[qid * 17 + 8 + 2 * tq]     = tf32r(e2 * inv);
                lg[qid * 17 + 8 + 2 * tq + 1] = tf32r(e3 * inv);
            }
            {
                bool rowOk = (qid < 4);
                float l[4];
                l[0] = d0[2] * 0.125f; l[1] = d0[3] * 0.125f;
                l[2] = colBad ? -1e30f : d1[2] * 0.125f;
                l[3] = colBad ? -1e30f : d1[3] * 0.125f;
                float mx = fmaxf(fmaxf(l[0], l[1]), fmaxf(l[2], l[3]));
                mx = fmaxf(mx, __shfl_xor_sync(0xffffffffu, mx, 1));
                mx = fmaxf(mx, __shfl_xor_sync(0xffffffffu, mx, 2));
                float e0 = __expf(l[0] - mx), e1 = __expf(l[1] - mx);
                float e2 = __expf(l[2] - mx), e3 = __expf(l[3] - mx);
                float s = e0 + e1 + e2 + e3;
                s += __shfl_xor_sync(0xffffffffu, s, 1);
                s += __shfl_xor_sync(0xffffffffu, s, 2);
                float inv = rowOk ? (1.f / s) : 0.f;
                lg[(qid + 8) * 17 + 2 * tq]         = tf32r(e0 * inv);
                lg[(qid + 8) * 17 + 2 * tq + 1]     = tf32r(e1 * inv);
                lg[(qid + 8) * 17 + 8 + 2 * tq]     = tf32r(e2 * inv);
                lg[(qid + 8) * 17 + 8 + 2 * tq + 1] = tf32r(e3 * inv);
            }
        } else if (grp < 7) {
            int n1 = n0 + 4;
            if (n1 < N) {
                int t2 = tid - 128;            // 0..255
                const float4* nb4 = (const float4*)(nbr + (size_t)n1 * 768);
                #pragma unroll
                for (int s = 0; s < 3; s++) {
                    int v = t2 + s * 256;      // 768 float4
                    float4 x = __ldcs(&nb4[v]);
                    x.x = tf32r(x.x); x.y = tf32r(x.y); x.z = tf32r(x.z); x.w = tf32r(x.w);
                    *(float4*)&sNFn[(v >> 4) * 68 + (v & 15) * 4] = x;
                }
                if (t2 < 48) sJn[t2] = idx[n1 * MNBR + t2];
            }
        }
        __syncthreads();

        // ---- P5: attn = W @ V MMA -> fp16 STG to g_att ----
        if (wid < 8) {
            int a = wid >> 1;
            int ntb = (wid & 1) * 4;
            const float* lg = sLG + a * 272;
            float af[2][4];
            #pragma unroll
            for (int s = 0; s < 2; s++) {
                int k = 8 * s + tq;
                af[s][0] = lg[qid * 17 + k];
                af[s][1] = lg[(qid + 8) * 17 + k];
                af[s][2] = lg[qid * 17 + k + 4];
                af[s][3] = lg[(qid + 8) * 17 + k + 4];
            }
            __half* go = g_att + (size_t)n0 * 768 + 12 * a * 64;
            #pragma unroll
            for (int j = 0; j < 4; j++) {
                int nt = ntb + j;
                float d[4] = {0.f, 0.f, 0.f, 0.f};
                #pragma unroll
                for (int s = 0; s < 2; s++) {
                    int kr = 12 * a + 8 * s + tq;
                    float b0 = sKQV[kr * 204 + 128 + 8 * nt + qid];
                    float b1 = sKQV[(kr + 4) * 204 + 128 + 8 * nt + qid];
                    mma8(d, af[s][0], af[s][1], af[s][2], af[s][3], b0, b1);
                }
                int col = 8 * nt + 2 * tq;
                unsigned u0 = packh2(d[0], d[1]);
                __stcs((unsigned int*)&go[qid * 64 + col], u0);
                if (qid < 4) {
                    unsigned u1 = packh2(d[2], d[3]);
                    __stcs((unsigned int*)&go[(qid + 8) * 64 + col], u1);
                }
            }
        }
        __syncthreads();   // sKQV reused next group
    }
}

// ---------------------------------------------------------------------------
// K_stats: S = att^T @ att + svec (per-channel), fp16 streaming loads.
// ---------------------------------------------------------------------------
__global__ __launch_bounds__(256, 4) void k_stats(int nChunks) {
    __shared__ float sA[128 * 68];
    __shared__ float ssv[64];
    int tid  = threadIdx.x;
    int wid  = tid >> 5;
    int lane = tid & 31;
    int qid  = lane >> 2;
    int tq   = lane & 3;
    int mt   = wid >> 1;
    int ntb  = (wid & 1) * 4;

    if (tid < 64) ssv[tid] = 0.f;
    float sacc[4][4];
    #pragma unroll
    for (int i = 0; i < 4; i++)
        #pragma unroll
        for (int j = 0; j < 4; j++) sacc[i][j] = 0.f;
    float sv[4] = {0.f, 0.f, 0.f, 0.f};

    for (int ch = blockIdx.x; ch < nChunks; ch += gridDim.x) {
        const uint2* ai2 = (const uint2*)(g_att + (size_t)ch * 8192);
        __syncthreads();
        #pragma unroll
        for (int s = 0; s < 8; s++) {
            int v = tid + s * 256;
            uint2 u = __ldcs(&ai2[v]);
            float2 f0 = unph2(u.x);
            float2 f1 = unph2(u.y);
            float4 x = {f0.x, f0.y, f1.x, f1.y};
            *(float4*)&sA[(v >> 4) * 68 + (v & 15) * 4] = x;
            sv[0] += x.x; sv[1] += x.y; sv[2] += x.z; sv[3] += x.w;
        }
        __syncthreads();
        #pragma unroll
        for (int ks = 0; ks < 16; ks++) {
            int kr = 8 * ks + tq;
            float a0 = sA[kr * 68 + 16 * mt + qid];
            float a1 = sA[kr * 68 + 16 * mt + qid + 8];
            float a2 = sA[(kr + 4) * 68 + 16 * mt + qid];
            float a3 = sA[(kr + 4) * 68 + 16 * mt + qid + 8];
            #pragma unroll
            for (int j = 0; j < 4; j++) {
                int nt = ntb + j;
                float b0 = sA[kr * 68 + 8 * nt + qid];
                float b1 = sA[(kr + 4) * 68 + 8 * nt + qid];
                mma8(sacc[j], a0, a1, a2, a3, b0, b1);
            }
        }
    }
    {
        int c4 = (tid & 15) * 4;
        atomicAdd(&ssv[c4],     sv[0]);
        atomicAdd(&ssv[c4 + 1], sv[1]);
        atomicAdd(&ssv[c4 + 2], sv[2]);
        atomicAdd(&ssv[c4 + 3], sv[3]);
    }
    #pragma unroll
    for (int j = 0; j < 4; j++) {
        int c1 = 16 * mt + qid;
        int c2 = 8 * (ntb + j) + 2 * tq;
        atomicAdd(&g_S[c1 * 64 + c2],           sacc[j][0]);
        atomicAdd(&g_S[c1 * 64 + c2 + 1],       sacc[j][1]);
        atomicAdd(&g_S[(c1 + 8) * 64 + c2],     sacc[j][2]);
        atomicAdd(&g_S[(c1 + 8) * 64 + c2 + 1], sacc[j][3]);
    }
    __syncthreads();
    if (tid < 64) atomicAdd(&g_svec[tid], ssv[tid]);
}

// ---------------------------------------------------------------------------
// K_bn1: moment trick, double-precision reduction.
// ---------------------------------------------------------------------------
__global__ void k_bn1(const float* __restrict__ bfc, const float* __restrict__ g1,
                      const float* __restrict__ b1, double invCnt) {
    __shared__ float sS[64 * 65];
    __shared__ float sw[64];
    __shared__ double red[4];
    int g = blockIdx.x;
    int i = threadIdx.x;
    sw[i] = g_Wfut[g * 64 + i];
    for (int l = i; l < 4096; l += 64)
        sS[(l >> 6) * 65 + (l & 63)] = g_S[l];
    __syncthreads();
    double y = 0.0;
    #pragma unroll 8
    for (int j = 0; j < 64; j++) y += (double)sS[i * 65 + j] * (double)sw[j];
    y *= (double)sw[i];
    double p = (double)sw[i] * (double)g_svec[i];
    #pragma unroll
    for (int off = 16; off > 0; off >>= 1) {
        y += __shfl_xor_sync(0xffffffffu, y, off);
        p += __shfl_xor_sync(0xffffffffu, p, off);
    }
    if ((i & 31) == 0) { red[(i >> 5) * 2] = y; red[(i >> 5) * 2 + 1] = p; }
    __syncthreads();
    if (i == 0) {
        double quad = red[0] + red[2];
        double lin  = red[1] + red[3];
        double b    = (double)bfc[g];
        double mean = lin * invCnt + b;
        double ex2  = (quad + 2.0 * b * lin) * invCnt + b * b;
        double var  = ex2 - mean * mean;
        double sc   = (double)g1[g] / sqrt(var + 1e-5);
        g_sc1[g] = (float)sc;
        g_sh1[g] = (float)((double)b1[g] - mean * sc);
    }
}

// ---------------------------------------------------------------------------
// K_gate: register-resident gated + tanh-sigmoid + reduction; fp16 att loads.
// ---------------------------------------------------------------------------
#define SMEM_GATE_FLOATS (48 * 68)
#define SMEM_GATE_BYTES (SMEM_GATE_FLOATS * 4)

__global__ __launch_bounds__(GBD, 3) void k_gate(const float* __restrict__ bfc, int N) {
    extern __shared__ float sm[];
    float* sA = sm;

    int tid  = threadIdx.x;
    int wid  = tid >> 5;
    int lane = tid & 31;
    int qid  = lane >> 2;
    int tq   = lane & 3;

    float bwf[8][2], bwh[8][2];
    float bbf[2], bbh[2];
    {
        int rf = wid * 8 + qid;
        int rh = 64 + wid * 8 + qid;
        float scf = g_sc1[rf], sch = g_sc1[rh];
        #pragma unroll
        for (int ks = 0; ks < 8; ks++) {
            bwf[ks][0] = tf32r(g_Wfut[rf * 64 + ks * 8 + tq] * scf);
            bwf[ks][1] = tf32r(g_Wfut[rf * 64 + ks * 8 + tq + 4] * scf);
            bwh[ks][0] = tf32r(g_Wfut[rh * 64 + ks * 8 + tq] * sch);
            bwh[ks][1] = tf32r(g_Wfut[rh * 64 + ks * 8 + tq + 4] * sch);
        }
        int cf = wid * 8 + 2 * tq;
        bbf[0] = bfc[cf]          * g_sc1[cf]          + g_sh1[cf];
        bbf[1] = bfc[cf + 1]      * g_sc1[cf + 1]      + g_sh1[cf + 1];
        bbh[0] = bfc[64 + cf]     * g_sc1[64 + cf]     + g_sh1[64 + cf];
        bbh[1] = bfc[64 + cf + 1] * g_sc1[64 + cf + 1] + g_sh1[64 + cf + 1];
    }
    float ls0 = 0.f, ls1 = 0.f, lq0 = 0.f, lq1 = 0.f;

    for (int grp = 0; grp < 8; grp++) {
        int n0 = blockIdx.x * APB + grp * 4;
        if (n0 >= N) break;

        const uint2* ai2 = (const uint2*)(g_att + (size_t)n0 * 768);
        #pragma unroll
        for (int s = 0; s < 3; s++) {
            int v = tid + s * GBD;
            uint2 u = __ldcs(&ai2[v]);
            float2 f0 = unph2(u.x);
            float2 f1 = unph2(u.y);
            float4 x = {f0.x, f0.y, f1.x, f1.y};
            *(float4*)&sA[(v >> 4) * 68 + (v & 15) * 4] = x;
        }
        __syncthreads();

        float acc[4][2];
        #pragma unroll
        for (int a = 0; a < 4; a++) { acc[a][0] = 0.f; acc[a][1] = 0.f; }

        #pragma unroll
        for (int mt = 0; mt < 3; mt++) {
            int r0 = 16 * mt + qid;
            float a[8][4];
            #pragma unroll
            for (int ks = 0; ks < 8; ks++) {
                int c0 = ks * 8 + tq;
                a[ks][0] = sA[r0 * 68 + c0];
                a[ks][1] = sA[(r0 + 8) * 68 + c0];
                a[ks][2] = sA[r0 * 68 + c0 + 4];
                a[ks][3] = sA[(r0 + 8) * 68 + c0 + 4];
            }
            float f[4] = {0.f, 0.f, 0.f, 0.f};
            float h[4] = {0.f, 0.f, 0.f, 0.f};
            #pragma unroll
            for (int ks = 0; ks < 8; ks++) {
                mma8(f, a[ks][0], a[ks][1], a[ks][2], a[ks][3], bwf[ks][0], bwf[ks][1]);
                mma8(h, a[ks][0], a[ks][1], a[ks][2], a[ks][3], bwh[ks][0], bwh[ks][1]);
            }
            float v0 = sigf(f[0] + bbf[0]) * spf2(h[0] + bbh[0]);
            float v1 = sigf(f[1] + bbf[1]) * spf2(h[1] + bbh[1]);
            float v2 = sigf(f[2] + bbf[0]) * spf2(h[2] + bbh[0]);
            float v3 = sigf(f[3] + bbf[1]) * spf2(h[3] + bbh[1]);
            if (mt == 0) {
                acc[0][0] += v0; acc[0][1] += v1;
                if (qid < 4) { acc[0][0] += v2; acc[0][1] += v3; }
                else         { acc[1][0] += v2; acc[1][1] += v3; }
            } else if (mt == 1) {
                acc[1][0] += v0; acc[1][1] += v1;
                acc[2][0] += v2; acc[2][1] += v3;
            } else {
                if (qid < 4) { acc[2][0] += v0; acc[2][1] += v1; }
                else         { acc[3][0] += v0; acc[3][1] += v1; }
                acc[3][0] += v2; acc[3][1] += v3;
            }
        }

        #pragma unroll
        for (int a = 0; a < 4; a++) {
            #pragma unroll
            for (int c = 0; c < 2; c++) {
                float v = acc[a][c];
                v += __shfl_xor_sync(0xffffffffu, v, 4);
                v += __shfl_xor_sync(0xffffffffu, v, 8);
                v += __shfl_xor_sync(0xffffffffu, v, 16);
                acc[a][c] = v;
            }
        }
        if (lane < 4) {
            int col = wid * 8 + 2 * lane;
            #pragma unroll
            for (int a = 0; a < 4; a++) {
                g_s[(size_t)(n0 + a) * 64 + col]     = acc[a][0];
                g_s[(size_t)(n0 + a) * 64 + col + 1] = acc[a][1];
                ls0 += acc[a][0]; lq0 += acc[a][0] * acc[a][0];
                ls1 += acc[a][1]; lq1 += acc[a][1] * acc[a][1];
            }
        }
        __syncthreads();
    }
    if (lane < 4) {
        int col = wid * 8 + 2 * lane;
        atomicAdd(&g_sum2[col],     ls0);
        atomicAdd(&g_sq2[col],      lq0);
        atomicAdd(&g_sum2[col + 1], ls1);
        atomicAdd(&g_sq2[col + 1],  lq1);
    }
}

// ---------------------------------------------------------------------------
// K_bn2: double-precision var computation.
// ---------------------------------------------------------------------------
__global__ void k_bn2(const float* __restrict__ g2, const float* __restrict__ b2, double invCnt) {
    int t = threadIdx.x;
    double m = (double)g_sum2[t] * invCnt;
    double v = (double)g_sq2[t] * invCnt - m * m;
    double sc = (double)g2[t] / sqrt(v + 1e-5);
    g_sc2[t] = (float)sc;
    g_sh2[t] = (float)((double)b2[t] - m * sc);
}

__global__ void k_final(const float* __restrict__ atom, float* __restrict__ out, int nVec) {
    int i = blockIdx.x * blockDim.x + threadIdx.x;
    if (i >= nVec) return;
    int c4 = (i & 15) * 4;
    float4 a = *(const float4*)&atom[(size_t)i * 4];
    float4 s = *(const float4*)&g_s[(size_t)i * 4];
    float4 o;
    o.x = spf2(a.x + s.x * g_sc2[c4]     + g_sh2[c4]);
    o.y = spf2(a.y + s.y * g_sc2[c4 + 1] + g_sh2[c4 + 1]);
    o.z = spf2(a.z + s.z * g_sc2[c4 + 2] + g_sh2[c4 + 2]);
    o.w = spf2(a.w + s.w * g_sc2[c4 + 3] + g_sh2[c4 + 3]);
    *(float4*)&out[(size_t)i * 4] = o;
}

// ---------------------------------------------------------------------------
extern "C" void kernel_launch(void* const* d_in, const int* in_sizes, int n_in,
                              void* d_out, int out_size) {
    const float* atom = (const float*)d_in[0];
    const float* nbr  = (const float*)d_in[1];
    const int*   idx  = (const int*)  d_in[2];
    const float* WK   = (const float*)d_in[3];
    const float* WQ   = (const float*)d_in[4];
    const float* WV   = (const float*)d_in[5];
    const float* WO   = (const float*)d_in[6];
    const float* Wfc  = (const float*)d_in[7];
    const float* bfc  = (const float*)d_in[8];
    const float* bn1g = (const float*)d_in[9];
    const float* bn1b = (const float*)d_in[10];
    const float* bn2g = (const float*)d_in[11];
    const float* bn2b = (const float*)d_in[12];
    float* out = (float*)d_out;

    int N = in_sizes[0] / ATOMF;
    int nChunks = (N * MNBR * ATOMF) / 8192;

    cudaFuncSetAttribute(k_main, cudaFuncAttributeMaxDynamicSharedMemorySize, SMEM_MAIN_BYTES);
    cudaFuncSetAttribute(k_gate, cudaFuncAttributeMaxDynamicSharedMemorySize, SMEM_GATE_BYTES);

    k_prep<<<192, 256>>>(WK, WQ, WV, Wfc, WO);
    k_projT<<<(N + 47) / 48, 384>>>(atom, N);
    k_main<<<(N + APB - 1) / APB, BD, SMEM_MAIN_BYTES>>>(nbr, idx, N);
    k_stats<<<1024, 256>>>(nChunks);
    k_bn1<<<128, 64>>>(bfc, bn1g, bn1b, 1.0 / ((double)N * MNBR));
    k_gate<<<(N + APB - 1) / APB, GBD, SMEM_GATE_BYTES>>>(bfc, N);
    k_bn2<<<1, 64>>>(bn2g, bn2b, 1.0 / (double)N);
    k_final<<<(N * ATOMF / 4 + 255) / 256, 256>>>(atom, out, N * ATOMF / 4);
}